// round 1
// baseline (speedup 1.0000x reference)
#include <cuda_runtime.h>

// Problem constants
#define BATCH 8
#define TT 2048
#define CC 256
#define NHEAD 8
#define HDIM 32
#define MTOT (BATCH * TT)   // 16384

// Scratch (allocation-free rule: device globals)
static __device__ float g_qkv[MTOT * 768];   // [m][0:256)=q, [256:512)=k, [512:768)=v
static __device__ float g_ctx[MTOT * CC];    // attention output, [B,T,C] layout

// ---------------------------------------------------------------------------
// QKV conv as GEMM: Y[m, mat*256+n] = sum_{tap,cin} x[b, t+tap-1, cin] * W[tap][cin][n] + bias[n]
// grid: (256 m-tiles, 12 n-tiles)  block: 256 threads, 64x64 tile, 4x4 per thread
// ---------------------------------------------------------------------------
__global__ __launch_bounds__(256) void qkv_conv_kernel(
    const float* __restrict__ X,
    const float* __restrict__ Wq, const float* __restrict__ bq,
    const float* __restrict__ Wk, const float* __restrict__ bk,
    const float* __restrict__ Wv, const float* __restrict__ bv)
{
    __shared__ float As[64][33];
    __shared__ float Bs[32][64];

    const int tid = threadIdx.x;
    const int m0 = blockIdx.x * 64;
    const int bI = m0 >> 11;           // T=2048 rows per batch
    const int t0 = m0 & (TT - 1);
    const int mat = blockIdx.y >> 2;   // 0=q, 1=k, 2=v
    const int n0 = (blockIdx.y & 3) * 64;

    const float* W    = (mat == 0) ? Wq : (mat == 1) ? Wk : Wv;
    const float* bias = (mat == 0) ? bq : (mat == 1) ? bk : bv;

    const int tm = tid >> 4;           // 0..15 -> rows tm*4..tm*4+3
    const int tn = tid & 15;           // 0..15 -> cols tn*4..tn*4+3

    float acc[4][4] = {};
    const float* Xb = X + (size_t)bI * TT * CC;

    for (int ko = 0; ko < 24; ++ko) {
        const int tap = ko >> 3;             // 0..2
        const int kk  = (ko & 7) << 5;       // cin offset, 0..224
        // load A tile: 64 rows x 32 cols (shifted input rows, zero at edges)
        #pragma unroll
        for (int u = 0; u < 2; ++u) {
            int idx = tid + u * 256;
            int row = idx >> 3;
            int col = (idx & 7) << 2;
            int t = t0 + row + tap - 1;
            float4 v = make_float4(0.f, 0.f, 0.f, 0.f);
            if (t >= 0 && t < TT)
                v = *reinterpret_cast<const float4*>(Xb + (size_t)t * CC + kk + col);
            As[row][col + 0] = v.x; As[row][col + 1] = v.y;
            As[row][col + 2] = v.z; As[row][col + 3] = v.w;
        }
        // load B tile: 32 x 64
        #pragma unroll
        for (int u = 0; u < 2; ++u) {
            int idx = tid + u * 256;
            int row = idx >> 4;
            int col = (idx & 15) << 2;
            *reinterpret_cast<float4*>(&Bs[row][col]) =
                *reinterpret_cast<const float4*>(W + tap * (CC * CC) + (size_t)(kk + row) * CC + n0 + col);
        }
        __syncthreads();
        #pragma unroll
        for (int k = 0; k < 32; ++k) {
            float a0 = As[tm * 4 + 0][k];
            float a1 = As[tm * 4 + 1][k];
            float a2 = As[tm * 4 + 2][k];
            float a3 = As[tm * 4 + 3][k];
            float4 bv4 = *reinterpret_cast<const float4*>(&Bs[k][tn * 4]);
            acc[0][0] += a0 * bv4.x; acc[0][1] += a0 * bv4.y; acc[0][2] += a0 * bv4.z; acc[0][3] += a0 * bv4.w;
            acc[1][0] += a1 * bv4.x; acc[1][1] += a1 * bv4.y; acc[1][2] += a1 * bv4.z; acc[1][3] += a1 * bv4.w;
            acc[2][0] += a2 * bv4.x; acc[2][1] += a2 * bv4.y; acc[2][2] += a2 * bv4.z; acc[2][3] += a2 * bv4.w;
            acc[3][0] += a3 * bv4.x; acc[3][1] += a3 * bv4.y; acc[3][2] += a3 * bv4.z; acc[3][3] += a3 * bv4.w;
        }
        __syncthreads();
    }

    #pragma unroll
    for (int i = 0; i < 4; ++i) {
        size_t m = m0 + tm * 4 + i;
        #pragma unroll
        for (int j = 0; j < 4; ++j) {
            int n = n0 + tn * 4 + j;
            g_qkv[m * 768 + mat * 256 + n] = acc[i][j] + bias[n];
        }
    }
}

// ---------------------------------------------------------------------------
// Flash attention: grid (32 q-tiles, 64 b*h), block 256.
// Q tile 64x32, loop over 32 KV tiles of 64 rows. Online softmax.
// Threads: tm=tid/16 owns 4 rows; tn=tid%16 owns 4 S-cols / 2 O-cols.
// ---------------------------------------------------------------------------
__global__ __launch_bounds__(256) void attn_kernel()
{
    __shared__ float Qs[64][36];
    __shared__ float Kts[32][68];   // K transposed: [d][key]
    __shared__ float Vs[64][34];
    __shared__ float Ps[64][68];

    const int tid = threadIdx.x;
    const int qt = blockIdx.x;          // 0..31
    const int bh = blockIdx.y;          // 0..63
    const int bI = bh >> 3;
    const int h  = bh & 7;
    const int q0 = qt * 64;

    const size_t base = (size_t)bI * TT * 768 + h * HDIM;
    const float* qp = g_qkv + base;          // +0   : q
    const float* kp = g_qkv + base + 256;    // +256 : k
    const float* vp = g_qkv + base + 512;    // +512 : v

    const int tm = tid >> 4;
    const int tn = tid & 15;
    const float scale = 0.17677669529663687f;   // 1/sqrt(32)

    // load Q (scaled): 64 rows x 32 = 512 float4
    #pragma unroll
    for (int u = 0; u < 2; ++u) {
        int idx = tid + u * 256;
        int row = idx >> 3;
        int col = (idx & 7) << 2;
        float4 q4 = *reinterpret_cast<const float4*>(qp + (size_t)(q0 + row) * 768 + col);
        Qs[row][col + 0] = q4.x * scale; Qs[row][col + 1] = q4.y * scale;
        Qs[row][col + 2] = q4.z * scale; Qs[row][col + 3] = q4.w * scale;
    }

    float m_i[4], l_i[4], o[4][2];
    #pragma unroll
    for (int i = 0; i < 4; ++i) {
        m_i[i] = -1e30f; l_i[i] = 0.f; o[i][0] = 0.f; o[i][1] = 0.f;
    }

    for (int j0 = 0; j0 < TT; j0 += 64) {
        __syncthreads();   // previous tile fully consumed (also orders Q writes on iter 0)
        // load K transposed + V
        #pragma unroll
        for (int u = 0; u < 2; ++u) {
            int idx = tid + u * 256;
            int row = idx >> 3;
            int col = (idx & 7) << 2;
            float4 k4 = *reinterpret_cast<const float4*>(kp + (size_t)(j0 + row) * 768 + col);
            Kts[col + 0][row] = k4.x; Kts[col + 1][row] = k4.y;
            Kts[col + 2][row] = k4.z; Kts[col + 3][row] = k4.w;
            float4 v4 = *reinterpret_cast<const float4*>(vp + (size_t)(j0 + row) * 768 + col);
            Vs[row][col + 0] = v4.x; Vs[row][col + 1] = v4.y;
            Vs[row][col + 2] = v4.z; Vs[row][col + 3] = v4.w;
        }
        __syncthreads();

        // S = Q @ K^T (64x64x32)
        float s[4][4] = {};
        #pragma unroll
        for (int d = 0; d < 32; ++d) {
            float a0 = Qs[tm * 4 + 0][d];
            float a1 = Qs[tm * 4 + 1][d];
            float a2 = Qs[tm * 4 + 2][d];
            float a3 = Qs[tm * 4 + 3][d];
            float4 kv4 = *reinterpret_cast<const float4*>(&Kts[d][tn * 4]);
            s[0][0] += a0 * kv4.x; s[0][1] += a0 * kv4.y; s[0][2] += a0 * kv4.z; s[0][3] += a0 * kv4.w;
            s[1][0] += a1 * kv4.x; s[1][1] += a1 * kv4.y; s[1][2] += a1 * kv4.z; s[1][3] += a1 * kv4.w;
            s[2][0] += a2 * kv4.x; s[2][1] += a2 * kv4.y; s[2][2] += a2 * kv4.z; s[2][3] += a2 * kv4.w;
            s[3][0] += a3 * kv4.x; s[3][1] += a3 * kv4.y; s[3][2] += a3 * kv4.z; s[3][3] += a3 * kv4.w;
        }

        // online softmax per row (16 lanes with same tm form one reduction group)
        #pragma unroll
        for (int i = 0; i < 4; ++i) {
            float mloc = fmaxf(fmaxf(s[i][0], s[i][1]), fmaxf(s[i][2], s[i][3]));
            #pragma unroll
            for (int off = 8; off >= 1; off >>= 1)
                mloc = fmaxf(mloc, __shfl_xor_sync(0xffffffffu, mloc, off));
            float mnew = fmaxf(m_i[i], mloc);
            float corr = __expf(m_i[i] - mnew);
            float p0 = __expf(s[i][0] - mnew);
            float p1 = __expf(s[i][1] - mnew);
            float p2 = __expf(s[i][2] - mnew);
            float p3 = __expf(s[i][3] - mnew);
            float lloc = p0 + p1 + p2 + p3;
            #pragma unroll
            for (int off = 8; off >= 1; off >>= 1)
                lloc += __shfl_xor_sync(0xffffffffu, lloc, off);
            l_i[i] = l_i[i] * corr + lloc;
            m_i[i] = mnew;
            o[i][0] *= corr; o[i][1] *= corr;
            float4 pw = make_float4(p0, p1, p2, p3);
            *reinterpret_cast<float4*>(&Ps[tm * 4 + i][tn * 4]) = pw;
        }
        __syncwarp();   // Ps produced & consumed within the same half-warp rows

        // O += P @ V (64x32x64); this thread: rows tm*4+i, cols tn*2 + {0,1}
        #pragma unroll
        for (int k = 0; k < 64; ++k) {
            float2 v2 = *reinterpret_cast<const float2*>(&Vs[k][tn * 2]);
            #pragma unroll
            for (int i = 0; i < 4; ++i) {
                float p = Ps[tm * 4 + i][k];
                o[i][0] += p * v2.x;
                o[i][1] += p * v2.y;
            }
        }
    }

    // normalize + write ctx [B,T,C]
    #pragma unroll
    for (int i = 0; i < 4; ++i) {
        float inv = 1.0f / l_i[i];
        size_t row = (size_t)bI * TT + q0 + tm * 4 + i;
        g_ctx[row * CC + h * HDIM + tn * 2 + 0] = o[i][0] * inv;
        g_ctx[row * CC + h * HDIM + tn * 2 + 1] = o[i][1] * inv;
    }
}

// ---------------------------------------------------------------------------
// Output conv + residual: out = x + conv1d(ctx, Wo) + bo
// grid: (256 m-tiles, 4 n-tiles)
// ---------------------------------------------------------------------------
__global__ __launch_bounds__(256) void out_conv_kernel(
    const float* __restrict__ Xres,
    const float* __restrict__ Wo, const float* __restrict__ bo,
    float* __restrict__ Y)
{
    __shared__ float As[64][33];
    __shared__ float Bs[32][64];

    const int tid = threadIdx.x;
    const int m0 = blockIdx.x * 64;
    const int bI = m0 >> 11;
    const int t0 = m0 & (TT - 1);
    const int n0 = blockIdx.y * 64;

    const int tm = tid >> 4;
    const int tn = tid & 15;

    float acc[4][4] = {};
    const float* Xb = g_ctx + (size_t)bI * TT * CC;

    for (int ko = 0; ko < 24; ++ko) {
        const int tap = ko >> 3;
        const int kk  = (ko & 7) << 5;
        #pragma unroll
        for (int u = 0; u < 2; ++u) {
            int idx = tid + u * 256;
            int row = idx >> 3;
            int col = (idx & 7) << 2;
            int t = t0 + row + tap - 1;
            float4 v = make_float4(0.f, 0.f, 0.f, 0.f);
            if (t >= 0 && t < TT)
                v = *reinterpret_cast<const float4*>(Xb + (size_t)t * CC + kk + col);
            As[row][col + 0] = v.x; As[row][col + 1] = v.y;
            As[row][col + 2] = v.z; As[row][col + 3] = v.w;
        }
        #pragma unroll
        for (int u = 0; u < 2; ++u) {
            int idx = tid + u * 256;
            int row = idx >> 4;
            int col = (idx & 15) << 2;
            *reinterpret_cast<float4*>(&Bs[row][col]) =
                *reinterpret_cast<const float4*>(Wo + tap * (CC * CC) + (size_t)(kk + row) * CC + n0 + col);
        }
        __syncthreads();
        #pragma unroll
        for (int k = 0; k < 32; ++k) {
            float a0 = As[tm * 4 + 0][k];
            float a1 = As[tm * 4 + 1][k];
            float a2 = As[tm * 4 + 2][k];
            float a3 = As[tm * 4 + 3][k];
            float4 bv4 = *reinterpret_cast<const float4*>(&Bs[k][tn * 4]);
            acc[0][0] += a0 * bv4.x; acc[0][1] += a0 * bv4.y; acc[0][2] += a0 * bv4.z; acc[0][3] += a0 * bv4.w;
            acc[1][0] += a1 * bv4.x; acc[1][1] += a1 * bv4.y; acc[1][2] += a1 * bv4.z; acc[1][3] += a1 * bv4.w;
            acc[2][0] += a2 * bv4.x; acc[2][1] += a2 * bv4.y; acc[2][2] += a2 * bv4.z; acc[2][3] += a2 * bv4.w;
            acc[3][0] += a3 * bv4.x; acc[3][1] += a3 * bv4.y; acc[3][2] += a3 * bv4.z; acc[3][3] += a3 * bv4.w;
        }
        __syncthreads();
    }

    #pragma unroll
    for (int i = 0; i < 4; ++i) {
        size_t m = m0 + tm * 4 + i;
        #pragma unroll
        for (int j = 0; j < 4; ++j) {
            int n = n0 + tn * 4 + j;
            Y[m * CC + n] = acc[i][j] + bo[n] + Xres[m * CC + n];
        }
    }
}

// ---------------------------------------------------------------------------
extern "C" void kernel_launch(void* const* d_in, const int* in_sizes, int n_in,
                              void* d_out, int out_size)
{
    const float* x  = (const float*)d_in[0];
    const float* Wq = (const float*)d_in[1];
    const float* bq = (const float*)d_in[2];
    const float* Wk = (const float*)d_in[3];
    const float* bk = (const float*)d_in[4];
    const float* Wv = (const float*)d_in[5];
    const float* bv = (const float*)d_in[6];
    const float* Wo = (const float*)d_in[7];
    const float* bo = (const float*)d_in[8];
    float* out = (float*)d_out;

    qkv_conv_kernel<<<dim3(256, 12), 256>>>(x, Wq, bq, Wk, bk, Wv, bv);
    attn_kernel<<<dim3(32, 64), 256>>>();
    out_conv_kernel<<<dim3(256, 4), 256>>>(x, Wo, bo, out);
}

// round 2
// speedup vs baseline: 2.5582x; 2.5582x over previous
#include <cuda_runtime.h>
#include <cstdint>

#define BATCH 8
#define TT 2048
#define CC 256
#define NHEAD 8
#define HDIM 32
#define MTOT (BATCH * TT)   // 16384

// Scratch (allocation-free rule: device globals)
static __device__ float g_qkv[MTOT * 768];   // [m][0:256)=q, [256:512)=k, [512:768)=v
static __device__ float g_ctx[MTOT * CC];    // attention output, [B,T,C]

// ---------------------------------------------------------------------------
// tf32 helpers
// ---------------------------------------------------------------------------
__device__ __forceinline__ uint32_t f2tf32(float f) {
    uint32_t r;
    asm("cvt.rna.tf32.f32 %0, %1;" : "=r"(r) : "f"(f));
    return r;
}

__device__ __forceinline__ void mma_tf32(float* d, const uint32_t* a, const uint32_t* b) {
    asm volatile(
        "mma.sync.aligned.m16n8k8.row.col.f32.tf32.tf32.f32 "
        "{%0,%1,%2,%3}, {%4,%5,%6,%7}, {%8,%9}, {%0,%1,%2,%3};"
        : "+f"(d[0]), "+f"(d[1]), "+f"(d[2]), "+f"(d[3])
        : "r"(a[0]), "r"(a[1]), "r"(a[2]), "r"(a[3]), "r"(b[0]), "r"(b[1]));
}

__device__ __forceinline__ uint4 cvt4(float4 v) {
    uint4 r;
    r.x = f2tf32(v.x); r.y = f2tf32(v.y); r.z = f2tf32(v.z); r.w = f2tf32(v.w);
    return r;
}

// ---------------------------------------------------------------------------
// Conv-as-GEMM with tf32 tensor cores.
// Block tile 128(M) x 64(N), K chunks of 32 (24 chunks = 3 taps x 256 cin).
// 256 threads = 8 warps (4x2), warp tile 32x32.
// Shared as "IS_OUT" template: out-conv reads g_ctx and adds residual.
// ---------------------------------------------------------------------------
template <bool IS_OUT>
__global__ __launch_bounds__(256) void conv_mma_kernel(
    const float* __restrict__ Xres,                   // residual (out-conv only)
    const float* __restrict__ Wq, const float* __restrict__ bq,
    const float* __restrict__ Wk, const float* __restrict__ bk,
    const float* __restrict__ Wv, const float* __restrict__ bv,
    const float* __restrict__ Xin,                    // A-matrix source
    float* __restrict__ Yout)                         // out-conv destination
{
    __shared__ uint32_t As[128][36];   // 128 rows x 32 k (tf32), pad->stride 36
    __shared__ uint32_t Bs[32][68];    // 32 k x 64 n, pad->stride 68

    const int tid = threadIdx.x;
    const int m0 = blockIdx.x * 128;
    const int bI = m0 >> 11;
    const int t0 = m0 & (TT - 1);

    int mat, n0;
    const float* W;
    const float* bias;
    if (IS_OUT) {
        mat = 0; n0 = blockIdx.y * 64;
        W = Wq; bias = bq;               // Wo, bo passed through Wq/bq slots
    } else {
        mat = blockIdx.y >> 2;
        n0 = (blockIdx.y & 3) * 64;
        W    = (mat == 0) ? Wq : (mat == 1) ? Wk : Wv;
        bias = (mat == 0) ? bq : (mat == 1) ? bk : bv;
    }

    const int warp = tid >> 5;
    const int lane = tid & 31;
    const int g  = lane >> 2;       // groupID 0..7
    const int tg = lane & 3;        // thread-in-group 0..3
    const int wm = warp >> 1;       // 0..3 -> m offset wm*32
    const int wn = warp & 1;        // 0..1 -> n offset wn*32

    const float* Xb = Xin + (size_t)bI * TT * CC;

    float acc[2][4][4];
    #pragma unroll
    for (int i = 0; i < 2; ++i)
        #pragma unroll
        for (int j = 0; j < 4; ++j)
            #pragma unroll
            for (int c = 0; c < 4; ++c) acc[i][j][c] = 0.f;

    for (int ko = 0; ko < 24; ++ko) {
        const int tap = ko >> 3;
        const int kk  = (ko & 7) << 5;
        // A tile: 128 rows x 32 cols, shifted by tap-1, zero at batch edges
        #pragma unroll
        for (int u = 0; u < 4; ++u) {
            int idx = tid + u * 256;
            int row = idx >> 3;
            int col = (idx & 7) << 2;
            int t = t0 + row + tap - 1;
            float4 v = make_float4(0.f, 0.f, 0.f, 0.f);
            if (t >= 0 && t < TT)
                v = *reinterpret_cast<const float4*>(Xb + (size_t)t * CC + kk + col);
            *reinterpret_cast<uint4*>(&As[row][col]) = cvt4(v);
        }
        // B tile: 32 x 64
        #pragma unroll
        for (int u = 0; u < 2; ++u) {
            int idx = tid + u * 256;
            int row = idx >> 4;
            int col = (idx & 15) << 2;
            float4 v = *reinterpret_cast<const float4*>(
                W + tap * (CC * CC) + (size_t)(kk + row) * CC + n0 + col);
            *reinterpret_cast<uint4*>(&Bs[row][col]) = cvt4(v);
        }
        __syncthreads();

        #pragma unroll
        for (int ks = 0; ks < 4; ++ks) {
            const int k0 = ks * 8;
            uint32_t a[2][4];
            #pragma unroll
            for (int mi = 0; mi < 2; ++mi) {
                int r0 = wm * 32 + mi * 16 + g;
                a[mi][0] = As[r0][k0 + tg];
                a[mi][1] = As[r0 + 8][k0 + tg];
                a[mi][2] = As[r0][k0 + tg + 4];
                a[mi][3] = As[r0 + 8][k0 + tg + 4];
            }
            uint32_t b[4][2];
            #pragma unroll
            for (int ni = 0; ni < 4; ++ni) {
                int col = wn * 32 + ni * 8 + g;
                b[ni][0] = Bs[k0 + tg][col];
                b[ni][1] = Bs[k0 + tg + 4][col];
            }
            #pragma unroll
            for (int mi = 0; mi < 2; ++mi)
                #pragma unroll
                for (int ni = 0; ni < 4; ++ni)
                    mma_tf32(acc[mi][ni], a[mi], b[ni]);
        }
        __syncthreads();
    }

    // Epilogue
    #pragma unroll
    for (int mi = 0; mi < 2; ++mi) {
        #pragma unroll
        for (int ni = 0; ni < 4; ++ni) {
            int row0 = m0 + wm * 32 + mi * 16 + g;
            int col  = wn * 32 + ni * 8 + 2 * tg;
            float b0 = bias[n0 + col];
            float b1 = bias[n0 + col + 1];
            if (IS_OUT) {
                size_t o0 = (size_t)row0 * CC + n0 + col;
                size_t o1 = (size_t)(row0 + 8) * CC + n0 + col;
                Yout[o0]     = acc[mi][ni][0] + b0 + Xres[o0];
                Yout[o0 + 1] = acc[mi][ni][1] + b1 + Xres[o0 + 1];
                Yout[o1]     = acc[mi][ni][2] + b0 + Xres[o1];
                Yout[o1 + 1] = acc[mi][ni][3] + b1 + Xres[o1 + 1];
            } else {
                size_t o0 = (size_t)row0 * 768 + mat * 256 + n0 + col;
                size_t o1 = (size_t)(row0 + 8) * 768 + mat * 256 + n0 + col;
                g_qkv[o0]     = acc[mi][ni][0] + b0;
                g_qkv[o0 + 1] = acc[mi][ni][1] + b1;
                g_qkv[o1]     = acc[mi][ni][2] + b0;
                g_qkv[o1 + 1] = acc[mi][ni][3] + b1;
            }
        }
    }
}

// ---------------------------------------------------------------------------
// Flash attention with tf32 mma.
// grid (32 q-tiles, 64 b*h), block 128 (4 warps). Q tile 64x32.
// Warp w owns S/O rows [w*16, w*16+16). S warp tile 16x64, O warp tile 16x32.
// ---------------------------------------------------------------------------
__global__ __launch_bounds__(128) void attn_mma_kernel()
{
    __shared__ uint32_t Qs[64][36];   // tf32, pre-scaled
    __shared__ uint32_t Ks[64][36];   // [key][d]
    __shared__ uint32_t Vs[64][36];   // [key][d]
    __shared__ uint32_t Ps[64][68];   // [qrow][key] tf32

    const int tid = threadIdx.x;
    const int warp = tid >> 5;
    const int lane = tid & 31;
    const int g  = lane >> 2;
    const int tg = lane & 3;

    const int qt = blockIdx.x;
    const int bh = blockIdx.y;
    const int bI = bh >> 3;
    const int h  = bh & 7;
    const int q0 = qt * 64;

    const size_t base = (size_t)bI * TT * 768 + h * HDIM;
    const float* qp = g_qkv + base;
    const float* kp = g_qkv + base + 256;
    const float* vp = g_qkv + base + 512;

    const float scale = 0.17677669529663687f;   // 1/sqrt(32)

    // load Q (scaled, tf32): 64x32 = 512 float4, 128 threads x4
    #pragma unroll
    for (int u = 0; u < 4; ++u) {
        int idx = tid + u * 128;
        int row = idx >> 3;
        int col = (idx & 7) << 2;
        float4 q4 = *reinterpret_cast<const float4*>(qp + (size_t)(q0 + row) * 768 + col);
        q4.x *= scale; q4.y *= scale; q4.z *= scale; q4.w *= scale;
        *reinterpret_cast<uint4*>(&Qs[row][col]) = cvt4(q4);
    }

    float m0r = -1e30f, m1r = -1e30f, l0r = 0.f, l1r = 0.f;
    float o[4][4];
    #pragma unroll
    for (int ni = 0; ni < 4; ++ni)
        #pragma unroll
        for (int c = 0; c < 4; ++c) o[ni][c] = 0.f;

    for (int j0 = 0; j0 < TT; j0 += 64) {
        __syncthreads();
        // load K,V tiles (tf32)
        #pragma unroll
        for (int u = 0; u < 4; ++u) {
            int idx = tid + u * 128;
            int row = idx >> 3;
            int col = (idx & 7) << 2;
            float4 k4 = *reinterpret_cast<const float4*>(kp + (size_t)(j0 + row) * 768 + col);
            *reinterpret_cast<uint4*>(&Ks[row][col]) = cvt4(k4);
            float4 v4 = *reinterpret_cast<const float4*>(vp + (size_t)(j0 + row) * 768 + col);
            *reinterpret_cast<uint4*>(&Vs[row][col]) = cvt4(v4);
        }
        __syncthreads();

        // S = Q K^T : warp tile 16x64, 8 n-tiles, k=32 (4 ksteps)
        float s[8][4];
        #pragma unroll
        for (int ni = 0; ni < 8; ++ni)
            #pragma unroll
            for (int c = 0; c < 4; ++c) s[ni][c] = 0.f;

        #pragma unroll
        for (int ks = 0; ks < 4; ++ks) {
            const int k0 = ks * 8;
            uint32_t a[4];
            int r0 = warp * 16 + g;
            a[0] = Qs[r0][k0 + tg];
            a[1] = Qs[r0 + 8][k0 + tg];
            a[2] = Qs[r0][k0 + tg + 4];
            a[3] = Qs[r0 + 8][k0 + tg + 4];
            #pragma unroll
            for (int ni = 0; ni < 8; ++ni) {
                uint32_t b[2];
                int kc = ni * 8 + g;            // key index
                b[0] = Ks[kc][k0 + tg];
                b[1] = Ks[kc][k0 + tg + 4];
                mma_tf32(s[ni], a, b);
            }
        }

        // online softmax; thread owns rows (warp*16+g) and (+8)
        float mx0 = -1e30f, mx1 = -1e30f;
        #pragma unroll
        for (int ni = 0; ni < 8; ++ni) {
            mx0 = fmaxf(mx0, fmaxf(s[ni][0], s[ni][1]));
            mx1 = fmaxf(mx1, fmaxf(s[ni][2], s[ni][3]));
        }
        mx0 = fmaxf(mx0, __shfl_xor_sync(0xffffffffu, mx0, 1));
        mx0 = fmaxf(mx0, __shfl_xor_sync(0xffffffffu, mx0, 2));
        mx1 = fmaxf(mx1, __shfl_xor_sync(0xffffffffu, mx1, 1));
        mx1 = fmaxf(mx1, __shfl_xor_sync(0xffffffffu, mx1, 2));

        float mn0 = fmaxf(m0r, mx0);
        float mn1 = fmaxf(m1r, mx1);
        float corr0 = __expf(m0r - mn0);
        float corr1 = __expf(m1r - mn1);

        float sum0 = 0.f, sum1 = 0.f;
        #pragma unroll
        for (int ni = 0; ni < 8; ++ni) {
            float p0 = __expf(s[ni][0] - mn0);
            float p1 = __expf(s[ni][1] - mn0);
            float p2 = __expf(s[ni][2] - mn1);
            float p3 = __expf(s[ni][3] - mn1);
            sum0 += p0 + p1; sum1 += p2 + p3;
            int row = warp * 16 + g;
            int col = ni * 8 + 2 * tg;
            uint2 w0; w0.x = f2tf32(p0); w0.y = f2tf32(p1);
            uint2 w1; w1.x = f2tf32(p2); w1.y = f2tf32(p3);
            *reinterpret_cast<uint2*>(&Ps[row][col]) = w0;
            *reinterpret_cast<uint2*>(&Ps[row + 8][col]) = w1;
        }
        sum0 += __shfl_xor_sync(0xffffffffu, sum0, 1);
        sum0 += __shfl_xor_sync(0xffffffffu, sum0, 2);
        sum1 += __shfl_xor_sync(0xffffffffu, sum1, 1);
        sum1 += __shfl_xor_sync(0xffffffffu, sum1, 2);

        l0r = l0r * corr0 + sum0;
        l1r = l1r * corr1 + sum1;
        m0r = mn0; m1r = mn1;
        #pragma unroll
        for (int ni = 0; ni < 4; ++ni) {
            o[ni][0] *= corr0; o[ni][1] *= corr0;
            o[ni][2] *= corr1; o[ni][3] *= corr1;
        }
        __syncwarp();   // Ps rows for this warp produced & consumed by same warp

        // O += P V : warp tile 16x32, 4 n-tiles, k=64 (8 ksteps)
        #pragma unroll
        for (int ks = 0; ks < 8; ++ks) {
            const int k0 = ks * 8;
            uint32_t a[4];
            int r0 = warp * 16 + g;
            a[0] = Ps[r0][k0 + tg];
            a[1] = Ps[r0 + 8][k0 + tg];
            a[2] = Ps[r0][k0 + tg + 4];
            a[3] = Ps[r0 + 8][k0 + tg + 4];
            #pragma unroll
            for (int ni = 0; ni < 4; ++ni) {
                uint32_t b[2];
                int nc = ni * 8 + g;            // d index
                b[0] = Vs[k0 + tg][nc];
                b[1] = Vs[k0 + tg + 4][nc];
                mma_tf32(o[ni], a, b);
            }
        }
    }

    // normalize + write ctx
    float inv0 = 1.0f / l0r;
    float inv1 = 1.0f / l1r;
    size_t row0 = (size_t)bI * TT + q0 + warp * 16 + g;
    #pragma unroll
    for (int ni = 0; ni < 4; ++ni) {
        int col = h * HDIM + ni * 8 + 2 * tg;
        float2 w0 = make_float2(o[ni][0] * inv0, o[ni][1] * inv0);
        float2 w1 = make_float2(o[ni][2] * inv1, o[ni][3] * inv1);
        *reinterpret_cast<float2*>(&g_ctx[row0 * CC + col]) = w0;
        *reinterpret_cast<float2*>(&g_ctx[(row0 + 8) * CC + col]) = w1;
    }
}

// ---------------------------------------------------------------------------
extern "C" void kernel_launch(void* const* d_in, const int* in_sizes, int n_in,
                              void* d_out, int out_size)
{
    const float* x  = (const float*)d_in[0];
    const float* Wq = (const float*)d_in[1];
    const float* bq = (const float*)d_in[2];
    const float* Wk = (const float*)d_in[3];
    const float* bk = (const float*)d_in[4];
    const float* Wv = (const float*)d_in[5];
    const float* bv = (const float*)d_in[6];
    const float* Wo = (const float*)d_in[7];
    const float* bo = (const float*)d_in[8];
    float* out = (float*)d_out;

    float* g_ctx_ptr;
    cudaGetSymbolAddress((void**)&g_ctx_ptr, g_ctx);

    conv_mma_kernel<false><<<dim3(128, 12), 256>>>(
        nullptr, Wq, bq, Wk, bk, Wv, bv, x, nullptr);
    attn_mma_kernel<<<dim3(32, 64), 128>>>();
    conv_mma_kernel<true><<<dim3(128, 4), 256>>>(
        x, Wo, bo, nullptr, nullptr, nullptr, nullptr, g_ctx_ptr, out);
}

// round 5
// speedup vs baseline: 4.7709x; 1.8650x over previous
#include <cuda_runtime.h>
#include <cuda_fp16.h>
#include <cstdint>

#define TT 2048
#define CC 256
#define MTOT 16384   // 8 * 2048

// Scratch (allocation-free rule: device globals). Half precision intermediates.
static __device__ __half g_qkv[MTOT * 768];  // [m][0:256)=q(pre-scaled),[256:512)=k,[512:768)=v
static __device__ __half g_ctx[MTOT * CC];   // attention output, [B,T,C]

// ---------------------------------------------------------------------------
__device__ __forceinline__ uint32_t smem_u32(const void* p) {
    return (uint32_t)__cvta_generic_to_shared(p);
}
__device__ __forceinline__ void ldm_x4(uint32_t* r, uint32_t addr) {
    asm volatile("ldmatrix.sync.aligned.m8n8.x4.shared.b16 {%0,%1,%2,%3}, [%4];"
                 : "=r"(r[0]), "=r"(r[1]), "=r"(r[2]), "=r"(r[3]) : "r"(addr));
}
__device__ __forceinline__ void ldm_x4t(uint32_t* r, uint32_t addr) {
    asm volatile("ldmatrix.sync.aligned.m8n8.x4.trans.shared.b16 {%0,%1,%2,%3}, [%4];"
                 : "=r"(r[0]), "=r"(r[1]), "=r"(r[2]), "=r"(r[3]) : "r"(addr));
}
__device__ __forceinline__ void mma_f16(float* d, const uint32_t* a, uint32_t b0, uint32_t b1) {
    asm volatile(
        "mma.sync.aligned.m16n8k16.row.col.f32.f16.f16.f32 "
        "{%0,%1,%2,%3}, {%4,%5,%6,%7}, {%8,%9}, {%0,%1,%2,%3};"
        : "+f"(d[0]), "+f"(d[1]), "+f"(d[2]), "+f"(d[3])
        : "r"(a[0]), "r"(a[1]), "r"(a[2]), "r"(a[3]), "r"(b0), "r"(b1));
}

// ---------------------------------------------------------------------------
// Conv-as-GEMM, fp16 mma. Block tile 128(M) x 64(N), K-chunk 32 (24 chunks).
// 256 threads = 8 warps (4m x 2n), warp tile 32x32.
// IS_OUT: A from g_ctx (half), adds residual, writes float out.
// ---------------------------------------------------------------------------
template <bool IS_OUT>
__global__ __launch_bounds__(256) void conv_mma_kernel(
    const float* __restrict__ Xres,
    const float* __restrict__ Wq, const float* __restrict__ bq,
    const float* __restrict__ Wk, const float* __restrict__ bk,
    const float* __restrict__ Wv, const float* __restrict__ bv,
    const float* __restrict__ Xf,
    float* __restrict__ Yout)
{
    __shared__ __align__(16) __half As[128][40];   // 80B row stride
    __shared__ __align__(16) __half Bs[32][72];    // 144B row stride

    const int tid = threadIdx.x;
    const int m0 = blockIdx.x * 128;
    const int bI = m0 >> 11;
    const int t0 = m0 & (TT - 1);

    int mat, n0;
    const float* W;
    const float* bias;
    if (IS_OUT) {
        mat = 3; n0 = blockIdx.y * 64;
        W = Wq; bias = bq;          // Wo, bo passed via Wq/bq slots
    } else {
        mat = blockIdx.y >> 2;
        n0 = (blockIdx.y & 3) * 64;
        W    = (mat == 0) ? Wq : (mat == 1) ? Wk : Wv;
        bias = (mat == 0) ? bq : (mat == 1) ? bk : bv;
    }

    const int warp = tid >> 5;
    const int lane = tid & 31;
    const int g  = lane >> 2;
    const int tg = lane & 3;
    const int wm = warp >> 1;
    const int wn = warp & 1;

    const int lr = lane & 7;
    const int a_roff = ((lane >> 3) & 1) * 8;
    const int a_coff = ((lane >> 4) & 1) * 8;
    const int b_koff = ((lane >> 3) & 1) * 8;
    const int b_noff = ((lane >> 4) & 1) * 8;

    uint32_t a_base[2], b_base[2];
    #pragma unroll
    for (int mi = 0; mi < 2; ++mi)
        a_base[mi] = smem_u32(&As[wm * 32 + mi * 16 + a_roff + lr][a_coff]);
    #pragma unroll
    for (int nb = 0; nb < 2; ++nb)
        b_base[nb] = smem_u32(&Bs[b_koff + lr][wn * 32 + nb * 16 + b_noff]);

    float acc[2][4][4];
    #pragma unroll
    for (int i = 0; i < 2; ++i)
        #pragma unroll
        for (int j = 0; j < 4; ++j)
            #pragma unroll
            for (int c = 0; c < 4; ++c) acc[i][j][c] = 0.f;

    for (int ko = 0; ko < 24; ++ko) {
        const int tap = ko >> 3;
        const int kk  = (ko & 7) << 5;
        // A tile 128 x 32 (shifted rows, zero at batch edges)
        #pragma unroll
        for (int u = 0; u < 4; ++u) {
            int idx = tid + u * 256;
            int row = idx >> 3;
            int col = (idx & 7) << 2;
            int t = t0 + row + tap - 1;
            __half2 h0, h1;
            if (t >= 0 && t < TT) {
                if (IS_OUT) {
                    const __half* src = g_ctx + ((size_t)bI * TT + t) * CC + kk + col;
                    h0 = *reinterpret_cast<const __half2*>(src);
                    h1 = *reinterpret_cast<const __half2*>(src + 2);
                } else {
                    float4 v = *reinterpret_cast<const float4*>(
                        Xf + ((size_t)bI * TT + t) * CC + kk + col);
                    h0 = __floats2half2_rn(v.x, v.y);
                    h1 = __floats2half2_rn(v.z, v.w);
                }
            } else {
                h0 = __floats2half2_rn(0.f, 0.f);
                h1 = h0;
            }
            *reinterpret_cast<__half2*>(&As[row][col])     = h0;
            *reinterpret_cast<__half2*>(&As[row][col + 2]) = h1;
        }
        // B tile 32 x 64
        #pragma unroll
        for (int u = 0; u < 2; ++u) {
            int idx = tid + u * 256;
            int row = idx >> 4;
            int col = (idx & 15) << 2;
            float4 v = *reinterpret_cast<const float4*>(
                W + tap * (CC * CC) + (size_t)(kk + row) * CC + n0 + col);
            *reinterpret_cast<__half2*>(&Bs[row][col])     = __floats2half2_rn(v.x, v.y);
            *reinterpret_cast<__half2*>(&Bs[row][col + 2]) = __floats2half2_rn(v.z, v.w);
        }
        __syncthreads();

        #pragma unroll
        for (int ks = 0; ks < 2; ++ks) {
            const int k0 = ks * 16;
            uint32_t a[2][4], b[2][4];
            #pragma unroll
            for (int mi = 0; mi < 2; ++mi) ldm_x4(a[mi], a_base[mi] + k0 * 2);
            #pragma unroll
            for (int nb = 0; nb < 2; ++nb) ldm_x4t(b[nb], b_base[nb] + k0 * 144);
            #pragma unroll
            for (int mi = 0; mi < 2; ++mi)
                #pragma unroll
                for (int nj = 0; nj < 4; ++nj)
                    mma_f16(acc[mi][nj], a[mi], b[nj >> 1][(nj & 1) * 2], b[nj >> 1][(nj & 1) * 2 + 1]);
        }
        __syncthreads();
    }

    // Epilogue
    const float qscale = (!IS_OUT && mat == 0) ? 0.17677669529663687f : 1.0f;
    #pragma unroll
    for (int mi = 0; mi < 2; ++mi) {
        #pragma unroll
        for (int nj = 0; nj < 4; ++nj) {
            int row0 = m0 + wm * 32 + mi * 16 + g;
            int col  = wn * 32 + nj * 8 + 2 * tg;
            float b0 = bias[n0 + col];
            float b1 = bias[n0 + col + 1];
            if (IS_OUT) {
                size_t o0 = (size_t)row0 * CC + n0 + col;
                size_t o1 = (size_t)(row0 + 8) * CC + n0 + col;
                float2 r0 = *reinterpret_cast<const float2*>(Xres + o0);
                float2 r1 = *reinterpret_cast<const float2*>(Xres + o1);
                float2 y0 = make_float2(acc[mi][nj][0] + b0 + r0.x, acc[mi][nj][1] + b1 + r0.y);
                float2 y1 = make_float2(acc[mi][nj][2] + b0 + r1.x, acc[mi][nj][3] + b1 + r1.y);
                *reinterpret_cast<float2*>(Yout + o0) = y0;
                *reinterpret_cast<float2*>(Yout + o1) = y1;
            } else {
                size_t o0 = (size_t)row0 * 768 + mat * 256 + n0 + col;
                size_t o1 = (size_t)(row0 + 8) * 768 + mat * 256 + n0 + col;
                *reinterpret_cast<__half2*>(&g_qkv[o0]) =
                    __floats2half2_rn((acc[mi][nj][0] + b0) * qscale, (acc[mi][nj][1] + b1) * qscale);
                *reinterpret_cast<__half2*>(&g_qkv[o1]) =
                    __floats2half2_rn((acc[mi][nj][2] + b0) * qscale, (acc[mi][nj][3] + b1) * qscale);
            }
        }
    }
}

// ---------------------------------------------------------------------------
// Flash attention, fp16 mma + ldmatrix.
// grid (32 q-tiles, 64 b*h), block 128 (4 warps). Warp owns 16 q rows.
// ---------------------------------------------------------------------------
__global__ __launch_bounds__(128) void attn_mma_kernel()
{
    __shared__ __align__(16) __half Qs[64][40];
    __shared__ __align__(16) __half Ks[64][40];
    __shared__ __align__(16) __half Vs[64][40];
    __shared__ __align__(16) __half Ps[64][72];

    const int tid = threadIdx.x;
    const int warp = tid >> 5;
    const int lane = tid & 31;
    const int g  = lane >> 2;
    const int tg = lane & 3;
    const int lr = lane & 7;

    const int qt = blockIdx.x;
    const int bh = blockIdx.y;
    const int bI = bh >> 3;
    const int h  = bh & 7;
    const int q0 = qt * 64;

    const __half* qp = g_qkv + (size_t)bI * TT * 768 + h * 32;
    const __half* kp = qp + 256;
    const __half* vp = qp + 512;

    const int a_roff = ((lane >> 3) & 1) * 8;
    const int a_coff = ((lane >> 4) & 1) * 8;
    const int kb_roff = ((lane >> 4) & 1) * 8;
    const int kb_coff = ((lane >> 3) & 1) * 8;
    const int vb_roff = ((lane >> 3) & 1) * 8;
    const int vb_coff = ((lane >> 4) & 1) * 8;

    const uint32_t qa_base = smem_u32(&Qs[warp * 16 + a_roff + lr][a_coff]);
    const uint32_t pa_base = smem_u32(&Ps[warp * 16 + a_roff + lr][a_coff]);
    uint32_t kb_base[4], vb_base[2];
    #pragma unroll
    for (int n2 = 0; n2 < 4; ++n2)
        kb_base[n2] = smem_u32(&Ks[n2 * 16 + kb_roff + lr][kb_coff]);
    #pragma unroll
    for (int nb = 0; nb < 2; ++nb)
        vb_base[nb] = smem_u32(&Vs[vb_roff + lr][nb * 16 + vb_coff]);

    // load Q tile (pre-scaled): 64 rows x 32 halves = 256 uint4, 2 per thread
    #pragma unroll
    for (int u = 0; u < 2; ++u) {
        int idx = tid + u * 128;
        int row = idx >> 2;          // 0..63
        int col = (idx & 3) * 8;     // 0,8,16,24  (uint4 = 8 halves)
        *reinterpret_cast<uint4*>(&Qs[row][col]) =
            *reinterpret_cast<const uint4*>(qp + (size_t)(q0 + row) * 768 + col);
    }

    float m0r = -1e30f, m1r = -1e30f, l0r = 0.f, l1r = 0.f;
    float o[4][4];
    #pragma unroll
    for (int nj = 0; nj < 4; ++nj)
        #pragma unroll
        for (int c = 0; c < 4; ++c) o[nj][c] = 0.f;

    for (int j0 = 0; j0 < TT; j0 += 64) {
        __syncthreads();
        #pragma unroll
        for (int u = 0; u < 2; ++u) {
            int idx = tid + u * 128;
            int row = idx >> 2;
            int col = (idx & 3) * 8;
            *reinterpret_cast<uint4*>(&Ks[row][col]) =
                *reinterpret_cast<const uint4*>(kp + (size_t)(j0 + row) * 768 + col);
            *reinterpret_cast<uint4*>(&Vs[row][col]) =
                *reinterpret_cast<const uint4*>(vp + (size_t)(j0 + row) * 768 + col);
        }
        __syncthreads();

        // S = Q K^T : warp 16x64, 2 ksteps
        float s[8][4];
        #pragma unroll
        for (int nj = 0; nj < 8; ++nj)
            #pragma unroll
            for (int c = 0; c < 4; ++c) s[nj][c] = 0.f;
        #pragma unroll
        for (int ks = 0; ks < 2; ++ks) {
            const int k0 = ks * 16;
            uint32_t a[4];
            ldm_x4(a, qa_base + k0 * 2);
            #pragma unroll
            for (int n2 = 0; n2 < 4; ++n2) {
                uint32_t b[4];
                ldm_x4(b, kb_base[n2] + k0 * 2);
                mma_f16(s[n2 * 2],     a, b[0], b[1]);
                mma_f16(s[n2 * 2 + 1], a, b[2], b[3]);
            }
        }

        // online softmax: thread owns rows warp*16+g and +8
        float mx0 = -1e30f, mx1 = -1e30f;
        #pragma unroll
        for (int nj = 0; nj < 8; ++nj) {
            mx0 = fmaxf(mx0, fmaxf(s[nj][0], s[nj][1]));
            mx1 = fmaxf(mx1, fmaxf(s[nj][2], s[nj][3]));
        }
        mx0 = fmaxf(mx0, __shfl_xor_sync(0xffffffffu, mx0, 1));
        mx0 = fmaxf(mx0, __shfl_xor_sync(0xffffffffu, mx0, 2));
        mx1 = fmaxf(mx1, __shfl_xor_sync(0xffffffffu, mx1, 1));
        mx1 = fmaxf(mx1, __shfl_xor_sync(0xffffffffu, mx1, 2));

        float mn0 = fmaxf(m0r, mx0);
        float mn1 = fmaxf(m1r, mx1);
        float corr0 = __expf(m0r - mn0);
        float corr1 = __expf(m1r - mn1);

        float sum0 = 0.f, sum1 = 0.f;
        const int prow = warp * 16 + g;
        #pragma unroll
        for (int nj = 0; nj < 8; ++nj) {
            float p0 = __expf(s[nj][0] - mn0);
            float p1 = __expf(s[nj][1] - mn0);
            float p2 = __expf(s[nj][2] - mn1);
            float p3 = __expf(s[nj][3] - mn1);
            sum0 += p0 + p1; sum1 += p2 + p3;
            int col = nj * 8 + 2 * tg;
            *reinterpret_cast<__half2*>(&Ps[prow][col])     = __floats2half2_rn(p0, p1);
            *reinterpret_cast<__half2*>(&Ps[prow + 8][col]) = __floats2half2_rn(p2, p3);
        }
        sum0 += __shfl_xor_sync(0xffffffffu, sum0, 1);
        sum0 += __shfl_xor_sync(0xffffffffu, sum0, 2);
        sum1 += __shfl_xor_sync(0xffffffffu, sum1, 1);
        sum1 += __shfl_xor_sync(0xffffffffu, sum1, 2);

        l0r = l0r * corr0 + sum0;
        l1r = l1r * corr1 + sum1;
        m0r = mn0; m1r = mn1;
        #pragma unroll
        for (int nj = 0; nj < 4; ++nj) {
            o[nj][0] *= corr0; o[nj][1] *= corr0;
            o[nj][2] *= corr1; o[nj][3] *= corr1;
        }
        __syncwarp();

        // O += P V : warp 16x32, 4 ksteps over keys
        #pragma unroll
        for (int ks = 0; ks < 4; ++ks) {
            const int k0 = ks * 16;
            uint32_t a[4];
            ldm_x4(a, pa_base + k0 * 2);
            #pragma unroll
            for (int nb = 0; nb < 2; ++nb) {
                uint32_t b[4];
                ldm_x4t(b, vb_base[nb] + k0 * 80);
                mma_f16(o[nb * 2],     a, b[0], b[1]);
                mma_f16(o[nb * 2 + 1], a, b[2], b[3]);
            }
        }
        __syncwarp();
    }

    // normalize + write ctx (half)
    float inv0 = 1.0f / l0r;
    float inv1 = 1.0f / l1r;
    size_t row0 = (size_t)bI * TT + q0 + warp * 16 + g;
    #pragma unroll
    for (int nj = 0; nj < 4; ++nj) {
        int col = h * 32 + nj * 8 + 2 * tg;
        *reinterpret_cast<__half2*>(&g_ctx[row0 * CC + col]) =
            __floats2half2_rn(o[nj][0] * inv0, o[nj][1] * inv0);
        *reinterpret_cast<__half2*>(&g_ctx[(row0 + 8) * CC + col]) =
            __floats2half2_rn(o[nj][2] * inv1, o[nj][3] * inv1);
    }
}

// ---------------------------------------------------------------------------
extern "C" void kernel_launch(void* const* d_in, const int* in_sizes, int n_in,
                              void* d_out, int out_size)
{
    const float* x  = (const float*)d_in[0];
    const float* Wq = (const float*)d_in[1];
    const float* bq = (const float*)d_in[2];
    const float* Wk = (const float*)d_in[3];
    const float* bk = (const float*)d_in[4];
    const float* Wv = (const float*)d_in[5];
    const float* bv = (const float*)d_in[6];
    const float* Wo = (const float*)d_in[7];
    const float* bo = (const float*)d_in[8];
    float* out = (float*)d_out;

    conv_mma_kernel<false><<<dim3(128, 12), 256>>>(
        nullptr, Wq, bq, Wk, bk, Wv, bv, x, nullptr);
    attn_mma_kernel<<<dim3(32, 64), 128>>>();
    conv_mma_kernel<true><<<dim3(128, 4), 256>>>(
        x, Wo, bo, nullptr, nullptr, nullptr, nullptr, nullptr, out);
}

// round 6
// speedup vs baseline: 5.9802x; 1.2535x over previous
#include <cuda_runtime.h>
#include <cuda_fp16.h>
#include <cstdint>

#define TT 2048
#define CC 256
#define MTOT 16384   // 8 * 2048

// Scratch (allocation-free rule: device globals). Half precision intermediates.
static __device__ __half g_qkv[MTOT * 768];  // [m][0:256)=q(pre-scaled),[256:512)=k,[512:768)=v
static __device__ __half g_ctx[MTOT * CC];   // attention output, [B,T,C]

// ---------------------------------------------------------------------------
__device__ __forceinline__ uint32_t smem_u32(const void* p) {
    return (uint32_t)__cvta_generic_to_shared(p);
}
__device__ __forceinline__ void ldm_x4(uint32_t* r, uint32_t addr) {
    asm volatile("ldmatrix.sync.aligned.m8n8.x4.shared.b16 {%0,%1,%2,%3}, [%4];"
                 : "=r"(r[0]), "=r"(r[1]), "=r"(r[2]), "=r"(r[3]) : "r"(addr));
}
__device__ __forceinline__ void ldm_x4t(uint32_t* r, uint32_t addr) {
    asm volatile("ldmatrix.sync.aligned.m8n8.x4.trans.shared.b16 {%0,%1,%2,%3}, [%4];"
                 : "=r"(r[0]), "=r"(r[1]), "=r"(r[2]), "=r"(r[3]) : "r"(addr));
}
__device__ __forceinline__ void mma_f16(float* d, const uint32_t* a, uint32_t b0, uint32_t b1) {
    asm volatile(
        "mma.sync.aligned.m16n8k16.row.col.f32.f16.f16.f32 "
        "{%0,%1,%2,%3}, {%4,%5,%6,%7}, {%8,%9}, {%0,%1,%2,%3};"
        : "+f"(d[0]), "+f"(d[1]), "+f"(d[2]), "+f"(d[3])
        : "r"(a[0]), "r"(a[1]), "r"(a[2]), "r"(a[3]), "r"(b0), "r"(b1));
}
__device__ __forceinline__ uint32_t h2pack(float a, float b) {
    __half2 h = __floats2half2_rn(a, b);
    return *reinterpret_cast<uint32_t*>(&h);
}
#define CP16(dst, src) asm volatile("cp.async.cg.shared.global [%0], [%1], 16;" :: "r"(dst), "l"(src))
#define CP_COMMIT() asm volatile("cp.async.commit_group;")
#define CP_WAIT1() asm volatile("cp.async.wait_group 1;")
#define CP_WAIT0() asm volatile("cp.async.wait_group 0;")

// ---------------------------------------------------------------------------
// Conv-as-GEMM, fp16 mma. Block tile 128(M) x 64(N).
// A tile (130 rows x 32 cin) loaded ONCE per cin-chunk, reused by all 3 taps.
// 256 threads = 8 warps (4m x 2n), warp tile 32x32.
// ---------------------------------------------------------------------------
template <bool IS_OUT>
__global__ __launch_bounds__(256) void conv_mma_kernel(
    const float* __restrict__ Xres,
    const float* __restrict__ Wq, const float* __restrict__ bq,
    const float* __restrict__ Wk, const float* __restrict__ bk,
    const float* __restrict__ Wv, const float* __restrict__ bv,
    const float* __restrict__ Xf,
    float* __restrict__ Yout)
{
    __shared__ __align__(16) __half As[130][40];     // rows t0-1 .. t0+128
    __shared__ __align__(16) __half Bs[3][32][72];   // per-tap weights

    const int tid = threadIdx.x;
    const int m0 = blockIdx.x * 128;
    const int bI = m0 >> 11;
    const int t0 = m0 & (TT - 1);

    int mat, n0;
    const float* W;
    const float* bias;
    if (IS_OUT) {
        mat = 3; n0 = blockIdx.y * 64;
        W = Wq; bias = bq;          // Wo, bo via Wq/bq slots
    } else {
        mat = blockIdx.y >> 2;
        n0 = (blockIdx.y & 3) * 64;
        W    = (mat == 0) ? Wq : (mat == 1) ? Wk : Wv;
        bias = (mat == 0) ? bq : (mat == 1) ? bk : bv;
    }

    const int warp = tid >> 5;
    const int lane = tid & 31;
    const int g  = lane >> 2;
    const int tg = lane & 3;
    const int wm = warp >> 1;
    const int wn = warp & 1;

    const int lr = lane & 7;
    const int a_roff = ((lane >> 3) & 1) * 8;
    const int a_coff = ((lane >> 4) & 1) * 8;
    const int b_koff = ((lane >> 3) & 1) * 8;
    const int b_noff = ((lane >> 4) & 1) * 8;

    uint32_t a_base[2], b_base[2];
    #pragma unroll
    for (int mi = 0; mi < 2; ++mi)
        a_base[mi] = smem_u32(&As[wm * 32 + mi * 16 + a_roff + lr][a_coff]);
    #pragma unroll
    for (int nb = 0; nb < 2; ++nb)
        b_base[nb] = smem_u32(&Bs[0][b_koff + lr][wn * 32 + nb * 16 + b_noff]);

    float acc[2][4][4];
    #pragma unroll
    for (int i = 0; i < 2; ++i)
        #pragma unroll
        for (int j = 0; j < 4; ++j)
            #pragma unroll
            for (int c = 0; c < 4; ++c) acc[i][j][c] = 0.f;

    for (int chunk = 0; chunk < 8; ++chunk) {
        const int kk = chunk << 5;
        // A tile: 130 rows x 32 cols, 16B STS units (520 units)
        #pragma unroll
        for (int u = 0; u < 3; ++u) {
            int unit = tid + u * 256;
            if (unit < 520) {
                int row  = unit >> 2;
                int colu = (unit & 3) * 8;
                int t = t0 + row - 1;
                uint4 st = make_uint4(0u, 0u, 0u, 0u);
                if (t >= 0 && t < TT) {
                    if (IS_OUT) {
                        st = *reinterpret_cast<const uint4*>(
                            g_ctx + ((size_t)bI * TT + t) * CC + kk + colu);
                    } else {
                        const float* src = Xf + ((size_t)bI * TT + t) * CC + kk + colu;
                        float4 f0 = *reinterpret_cast<const float4*>(src);
                        float4 f1 = *reinterpret_cast<const float4*>(src + 4);
                        st.x = h2pack(f0.x, f0.y); st.y = h2pack(f0.z, f0.w);
                        st.z = h2pack(f1.x, f1.y); st.w = h2pack(f1.z, f1.w);
                    }
                }
                *reinterpret_cast<uint4*>(&As[row][colu]) = st;
            }
        }
        // B tiles: 3 taps x 32 x 64 (768 units)
        #pragma unroll
        for (int u = 0; u < 3; ++u) {
            int unit = tid + u * 256;
            int tap = unit >> 8;
            int rem = unit & 255;
            int row  = rem >> 3;
            int colu = (rem & 7) * 8;
            const float* src = W + tap * (CC * CC) + (size_t)(kk + row) * CC + n0 + colu;
            float4 f0 = *reinterpret_cast<const float4*>(src);
            float4 f1 = *reinterpret_cast<const float4*>(src + 4);
            uint4 st;
            st.x = h2pack(f0.x, f0.y); st.y = h2pack(f0.z, f0.w);
            st.z = h2pack(f1.x, f1.y); st.w = h2pack(f1.z, f1.w);
            *reinterpret_cast<uint4*>(&Bs[tap][row][colu]) = st;
        }
        __syncthreads();

        #pragma unroll
        for (int tap = 0; tap < 3; ++tap) {
            #pragma unroll
            for (int ks = 0; ks < 2; ++ks) {
                uint32_t a[2][4], b[2][4];
                #pragma unroll
                for (int mi = 0; mi < 2; ++mi)
                    ldm_x4(a[mi], a_base[mi] + tap * 80 + ks * 32);
                #pragma unroll
                for (int nb = 0; nb < 2; ++nb)
                    ldm_x4t(b[nb], b_base[nb] + tap * 4608 + ks * 16 * 144);
                #pragma unroll
                for (int mi = 0; mi < 2; ++mi)
                    #pragma unroll
                    for (int nj = 0; nj < 4; ++nj)
                        mma_f16(acc[mi][nj], a[mi],
                                b[nj >> 1][(nj & 1) * 2], b[nj >> 1][(nj & 1) * 2 + 1]);
            }
        }
        __syncthreads();
    }

    // Epilogue
    const float qscale = (!IS_OUT && mat == 0) ? 0.17677669529663687f : 1.0f;
    #pragma unroll
    for (int mi = 0; mi < 2; ++mi) {
        #pragma unroll
        for (int nj = 0; nj < 4; ++nj) {
            int row0 = m0 + wm * 32 + mi * 16 + g;
            int col  = wn * 32 + nj * 8 + 2 * tg;
            float b0 = bias[n0 + col];
            float b1 = bias[n0 + col + 1];
            if (IS_OUT) {
                size_t o0 = (size_t)row0 * CC + n0 + col;
                size_t o1 = (size_t)(row0 + 8) * CC + n0 + col;
                float2 r0 = *reinterpret_cast<const float2*>(Xres + o0);
                float2 r1 = *reinterpret_cast<const float2*>(Xres + o1);
                float2 y0 = make_float2(acc[mi][nj][0] + b0 + r0.x, acc[mi][nj][1] + b1 + r0.y);
                float2 y1 = make_float2(acc[mi][nj][2] + b0 + r1.x, acc[mi][nj][3] + b1 + r1.y);
                *reinterpret_cast<float2*>(Yout + o0) = y0;
                *reinterpret_cast<float2*>(Yout + o1) = y1;
            } else {
                size_t o0 = (size_t)row0 * 768 + mat * 256 + n0 + col;
                size_t o1 = (size_t)(row0 + 8) * 768 + mat * 256 + n0 + col;
                *reinterpret_cast<__half2*>(&g_qkv[o0]) =
                    __floats2half2_rn((acc[mi][nj][0] + b0) * qscale, (acc[mi][nj][1] + b1) * qscale);
                *reinterpret_cast<__half2*>(&g_qkv[o1]) =
                    __floats2half2_rn((acc[mi][nj][2] + b0) * qscale, (acc[mi][nj][3] + b1) * qscale);
            }
        }
    }
}

// ---------------------------------------------------------------------------
// Flash attention, fp16 mma, register-resident P, cp.async double-buffered KV.
// grid (16 q-tiles, 64 b*h), block 256 (8 warps). Warp owns 16 q rows (128/block).
// ---------------------------------------------------------------------------
__global__ __launch_bounds__(256) void attn_mma_kernel()
{
    __shared__ __align__(16) __half Qs[128][40];
    __shared__ __align__(16) __half Ks[2][64][40];
    __shared__ __align__(16) __half Vs[2][64][40];

    const int tid = threadIdx.x;
    const int warp = tid >> 5;
    const int lane = tid & 31;
    const int g  = lane >> 2;
    const int tg = lane & 3;
    const int lr = lane & 7;

    const int qt = blockIdx.x;
    const int bh = blockIdx.y;
    const int bI = bh >> 3;
    const int h  = bh & 7;
    const int q0 = qt * 128;

    const __half* qp = g_qkv + (size_t)bI * TT * 768 + h * 32;
    const __half* kp = qp + 256;
    const __half* vp = qp + 512;

    const int a_roff = ((lane >> 3) & 1) * 8;
    const int a_coff = ((lane >> 4) & 1) * 8;
    const int kb_roff = ((lane >> 4) & 1) * 8;
    const int kb_coff = ((lane >> 3) & 1) * 8;
    const int vb_roff = ((lane >> 3) & 1) * 8;
    const int vb_coff = ((lane >> 4) & 1) * 8;

    const uint32_t qa_base = smem_u32(&Qs[warp * 16 + a_roff + lr][a_coff]);
    uint32_t kb_base[2][4], vb_base[2][2];
    #pragma unroll
    for (int bf = 0; bf < 2; ++bf) {
        #pragma unroll
        for (int n2 = 0; n2 < 4; ++n2)
            kb_base[bf][n2] = smem_u32(&Ks[bf][n2 * 16 + kb_roff + lr][kb_coff]);
        #pragma unroll
        for (int nb = 0; nb < 2; ++nb)
            vb_base[bf][nb] = smem_u32(&Vs[bf][vb_roff + lr][nb * 16 + vb_coff]);
    }

    // load Q tile: 128 rows x 32 halves = 512 uint4, 2 per thread
    #pragma unroll
    for (int u = 0; u < 2; ++u) {
        int idx = tid + u * 256;
        int row = idx >> 2;
        int col = (idx & 3) * 8;
        *reinterpret_cast<uint4*>(&Qs[row][col]) =
            *reinterpret_cast<const uint4*>(qp + (size_t)(q0 + row) * 768 + col);
    }

    // cp.async KV prefetch helper pattern: K for u=0, V for u=1; one uint4/thread each
    const int kv_row = tid >> 2;
    const int kv_col = (tid & 3) * 8;
    {   // stage 0
        CP16(smem_u32(&Ks[0][kv_row][kv_col]),
             kp + (size_t)kv_row * 768 + kv_col);
        CP16(smem_u32(&Vs[0][kv_row][kv_col]),
             vp + (size_t)kv_row * 768 + kv_col);
        CP_COMMIT();
    }
    __syncthreads();   // Qs visible

    // Q fragments are loop-invariant: hoist to registers
    uint32_t qa[2][4];
    ldm_x4(qa[0], qa_base);
    ldm_x4(qa[1], qa_base + 32);

    float m0r = -1e30f, m1r = -1e30f, l0r = 0.f, l1r = 0.f;
    float o[4][4];
    #pragma unroll
    for (int nj = 0; nj < 4; ++nj)
        #pragma unroll
        for (int c = 0; c < 4; ++c) o[nj][c] = 0.f;

    for (int jt = 0; jt < 32; ++jt) {
        const int buf = jt & 1;
        if (jt + 1 < 32) {
            size_t roff = (size_t)((jt + 1) * 64 + kv_row) * 768 + kv_col;
            CP16(smem_u32(&Ks[buf ^ 1][kv_row][kv_col]), kp + roff);
            CP16(smem_u32(&Vs[buf ^ 1][kv_row][kv_col]), vp + roff);
            CP_COMMIT();
            CP_WAIT1();
        } else {
            CP_WAIT0();
        }
        __syncthreads();

        // S = Q K^T : warp 16x64
        float s[8][4];
        #pragma unroll
        for (int nj = 0; nj < 8; ++nj)
            #pragma unroll
            for (int c = 0; c < 4; ++c) s[nj][c] = 0.f;
        #pragma unroll
        for (int ks = 0; ks < 2; ++ks) {
            #pragma unroll
            for (int n2 = 0; n2 < 4; ++n2) {
                uint32_t b[4];
                ldm_x4(b, kb_base[buf][n2] + ks * 32);
                mma_f16(s[n2 * 2],     qa[ks], b[0], b[1]);
                mma_f16(s[n2 * 2 + 1], qa[ks], b[2], b[3]);
            }
        }

        // online softmax (rows warp*16+g, +8)
        float mx0 = -1e30f, mx1 = -1e30f;
        #pragma unroll
        for (int nj = 0; nj < 8; ++nj) {
            mx0 = fmaxf(mx0, fmaxf(s[nj][0], s[nj][1]));
            mx1 = fmaxf(mx1, fmaxf(s[nj][2], s[nj][3]));
        }
        mx0 = fmaxf(mx0, __shfl_xor_sync(0xffffffffu, mx0, 1));
        mx0 = fmaxf(mx0, __shfl_xor_sync(0xffffffffu, mx0, 2));
        mx1 = fmaxf(mx1, __shfl_xor_sync(0xffffffffu, mx1, 1));
        mx1 = fmaxf(mx1, __shfl_xor_sync(0xffffffffu, mx1, 2));

        float mn0 = fmaxf(m0r, mx0);
        float mn1 = fmaxf(m1r, mx1);
        float corr0 = __expf(m0r - mn0);
        float corr1 = __expf(m1r - mn1);

        float sum0 = 0.f, sum1 = 0.f;
        #pragma unroll
        for (int nj = 0; nj < 8; ++nj) {
            s[nj][0] = __expf(s[nj][0] - mn0);
            s[nj][1] = __expf(s[nj][1] - mn0);
            s[nj][2] = __expf(s[nj][2] - mn1);
            s[nj][3] = __expf(s[nj][3] - mn1);
            sum0 += s[nj][0] + s[nj][1];
            sum1 += s[nj][2] + s[nj][3];
        }
        sum0 += __shfl_xor_sync(0xffffffffu, sum0, 1);
        sum0 += __shfl_xor_sync(0xffffffffu, sum0, 2);
        sum1 += __shfl_xor_sync(0xffffffffu, sum1, 1);
        sum1 += __shfl_xor_sync(0xffffffffu, sum1, 2);

        l0r = l0r * corr0 + sum0;
        l1r = l1r * corr1 + sum1;
        m0r = mn0; m1r = mn1;
        #pragma unroll
        for (int nj = 0; nj < 4; ++nj) {
            o[nj][0] *= corr0; o[nj][1] *= corr0;
            o[nj][2] *= corr1; o[nj][3] *= corr1;
        }

        // pack P into A fragments (register pipeline: S C-frag == PV A-frag)
        uint32_t pa[4][4];
        #pragma unroll
        for (int kc = 0; kc < 4; ++kc) {
            pa[kc][0] = h2pack(s[2 * kc][0],     s[2 * kc][1]);
            pa[kc][1] = h2pack(s[2 * kc][2],     s[2 * kc][3]);
            pa[kc][2] = h2pack(s[2 * kc + 1][0], s[2 * kc + 1][1]);
            pa[kc][3] = h2pack(s[2 * kc + 1][2], s[2 * kc + 1][3]);
        }

        // O += P V
        #pragma unroll
        for (int kc = 0; kc < 4; ++kc) {
            #pragma unroll
            for (int nb = 0; nb < 2; ++nb) {
                uint32_t b[4];
                ldm_x4t(b, vb_base[buf][nb] + kc * 16 * 80);
                mma_f16(o[nb * 2],     pa[kc], b[0], b[1]);
                mma_f16(o[nb * 2 + 1], pa[kc], b[2], b[3]);
            }
        }
        __syncthreads();   // buf fully consumed before next prefetch overwrites
    }

    // normalize + write ctx (half)
    float inv0 = 1.0f / l0r;
    float inv1 = 1.0f / l1r;
    size_t row0 = (size_t)bI * TT + q0 + warp * 16 + g;
    #pragma unroll
    for (int nj = 0; nj < 4; ++nj) {
        int col = h * 32 + nj * 8 + 2 * tg;
        *reinterpret_cast<__half2*>(&g_ctx[row0 * CC + col]) =
            __floats2half2_rn(o[nj][0] * inv0, o[nj][1] * inv0);
        *reinterpret_cast<__half2*>(&g_ctx[(row0 + 8) * CC + col]) =
            __floats2half2_rn(o[nj][2] * inv1, o[nj][3] * inv1);
    }
}

// ---------------------------------------------------------------------------
extern "C" void kernel_launch(void* const* d_in, const int* in_sizes, int n_in,
                              void* d_out, int out_size)
{
    const float* x  = (const float*)d_in[0];
    const float* Wq = (const float*)d_in[1];
    const float* bq = (const float*)d_in[2];
    const float* Wk = (const float*)d_in[3];
    const float* bk = (const float*)d_in[4];
    const float* Wv = (const float*)d_in[5];
    const float* bv = (const float*)d_in[6];
    const float* Wo = (const float*)d_in[7];
    const float* bo = (const float*)d_in[8];
    float* out = (float*)d_out;

    conv_mma_kernel<false><<<dim3(128, 12), 256>>>(
        nullptr, Wq, bq, Wk, bk, Wv, bv, x, nullptr);
    attn_mma_kernel<<<dim3(16, 64), 256>>>();
    conv_mma_kernel<true><<<dim3(128, 4), 256>>>(
        x, Wo, bo, nullptr, nullptr, nullptr, nullptr, nullptr, out);
}

// round 7
// speedup vs baseline: 7.1105x; 1.1890x over previous
#include <cuda_runtime.h>
#include <cuda_fp16.h>
#include <cstdint>

#define TT 2048
#define CC 256
#define MTOT 16384   // 8 * 2048

// Scratch (allocation-free rule: device globals)
static __device__ __half g_qkv[MTOT * 768];        // q(pre-scaled)|k|v per row
static __device__ __half g_ctx[MTOT * CC];         // attention output
static __device__ __half g_xh[MTOT * CC];          // x converted to half
static __device__ __half g_wh[4 * 3 * CC * CC];    // Wq,Wk,Wv,Wo converted to half

// ---------------------------------------------------------------------------
__device__ __forceinline__ uint32_t smem_u32(const void* p) {
    return (uint32_t)__cvta_generic_to_shared(p);
}
__device__ __forceinline__ void ldm_x4(uint32_t* r, uint32_t addr) {
    asm volatile("ldmatrix.sync.aligned.m8n8.x4.shared.b16 {%0,%1,%2,%3}, [%4];"
                 : "=r"(r[0]), "=r"(r[1]), "=r"(r[2]), "=r"(r[3]) : "r"(addr));
}
__device__ __forceinline__ void ldm_x4t(uint32_t* r, uint32_t addr) {
    asm volatile("ldmatrix.sync.aligned.m8n8.x4.trans.shared.b16 {%0,%1,%2,%3}, [%4];"
                 : "=r"(r[0]), "=r"(r[1]), "=r"(r[2]), "=r"(r[3]) : "r"(addr));
}
__device__ __forceinline__ void mma_f16(float* d, const uint32_t* a, uint32_t b0, uint32_t b1) {
    asm volatile(
        "mma.sync.aligned.m16n8k16.row.col.f32.f16.f16.f32 "
        "{%0,%1,%2,%3}, {%4,%5,%6,%7}, {%8,%9}, {%0,%1,%2,%3};"
        : "+f"(d[0]), "+f"(d[1]), "+f"(d[2]), "+f"(d[3])
        : "r"(a[0]), "r"(a[1]), "r"(a[2]), "r"(a[3]), "r"(b0), "r"(b1));
}
__device__ __forceinline__ uint32_t h2pack(float a, float b) {
    __half2 h = __floats2half2_rn(a, b);
    return *reinterpret_cast<uint32_t*>(&h);
}
#define CP16(dst, src) asm volatile("cp.async.cg.shared.global [%0], [%1], 16;" :: "r"(dst), "l"(src))
#define CP16Z(dst, src, sz) asm volatile("cp.async.cg.shared.global [%0], [%1], 16, %2;" :: "r"(dst), "l"(src), "r"(sz))
#define CP_COMMIT() asm volatile("cp.async.commit_group;")
#define CP_WAIT1() asm volatile("cp.async.wait_group 1;")
#define CP_WAIT0() asm volatile("cp.async.wait_group 0;")

// ---------------------------------------------------------------------------
// One-shot conversion: x -> g_xh, W{q,k,v,o} -> g_wh. Unit = 8 floats.
// ---------------------------------------------------------------------------
#define XUNITS 524288   // MTOT*CC/8
#define WUNITS_PER 24576
__global__ __launch_bounds__(256) void cvt_kernel(
    const float* __restrict__ x,
    const float* __restrict__ Wq, const float* __restrict__ Wk,
    const float* __restrict__ Wv, const float* __restrict__ Wo)
{
    int i = blockIdx.x * blockDim.x + threadIdx.x;
    const float* src;
    __half* dst;
    if (i < XUNITS) {
        src = x + (size_t)i * 8;
        dst = g_xh + (size_t)i * 8;
    } else {
        int w = i - XUNITS;
        if (w >= 4 * WUNITS_PER) return;
        int m = w / WUNITS_PER;
        int r = w - m * WUNITS_PER;
        const float* W = (m == 0) ? Wq : (m == 1) ? Wk : (m == 2) ? Wv : Wo;
        src = W + (size_t)r * 8;
        dst = g_wh + (size_t)m * (3 * CC * CC) + (size_t)r * 8;
    }
    float4 f0 = *reinterpret_cast<const float4*>(src);
    float4 f1 = *reinterpret_cast<const float4*>(src + 4);
    uint4 st;
    st.x = h2pack(f0.x, f0.y); st.y = h2pack(f0.z, f0.w);
    st.z = h2pack(f1.x, f1.y); st.w = h2pack(f1.z, f1.w);
    *reinterpret_cast<uint4*>(dst) = st;
}

// ---------------------------------------------------------------------------
// Conv-as-GEMM, fp16 mma, cp.async double-buffered.
// Block tile 128(M) x 64(N). A tile 130 rows reused by all 3 taps.
// 256 threads = 8 warps (4m x 2n), warp tile 32x32.
// ---------------------------------------------------------------------------
#define AS_STRIDE 40
#define BS_STRIDE 72
#define AS_BUFB (130 * AS_STRIDE * 2)        // bytes per A buffer
#define BS_BUFB (3 * 32 * BS_STRIDE * 2)     // bytes per B buffer

template <bool IS_OUT>
__global__ __launch_bounds__(256) void conv_mma_kernel(
    const float* __restrict__ Xres,
    const float* __restrict__ bq, const float* __restrict__ bk,
    const float* __restrict__ bv,
    float* __restrict__ Yout)
{
    __shared__ __align__(16) __half As[2][130][AS_STRIDE];
    __shared__ __align__(16) __half Bs[2][3][32][BS_STRIDE];

    const int tid = threadIdx.x;
    const int m0 = blockIdx.x * 128;
    const int bI = m0 >> 11;
    const int t0 = m0 & (TT - 1);

    int mat, n0;
    const float* bias;
    if (IS_OUT) {
        mat = 3; n0 = blockIdx.y * 64;
        bias = bq;                     // bo via bq slot
    } else {
        mat = blockIdx.y >> 2;
        n0 = (blockIdx.y & 3) * 64;
        bias = (mat == 0) ? bq : (mat == 1) ? bk : bv;
    }

    const __half* Abase = (IS_OUT ? g_ctx : g_xh) + (size_t)bI * TT * CC;
    const __half* Wbase = g_wh + (size_t)mat * (3 * CC * CC) + n0;

    const int warp = tid >> 5;
    const int lane = tid & 31;
    const int g  = lane >> 2;
    const int tg = lane & 3;
    const int wm = warp >> 1;
    const int wn = warp & 1;

    const int lr = lane & 7;
    const int a_roff = ((lane >> 3) & 1) * 8;
    const int a_coff = ((lane >> 4) & 1) * 8;
    const int b_koff = ((lane >> 3) & 1) * 8;
    const int b_noff = ((lane >> 4) & 1) * 8;

    uint32_t a_base0[2], b_base0[2];
    #pragma unroll
    for (int mi = 0; mi < 2; ++mi)
        a_base0[mi] = smem_u32(&As[0][wm * 32 + mi * 16 + a_roff + lr][a_coff]);
    #pragma unroll
    for (int nb = 0; nb < 2; ++nb)
        b_base0[nb] = smem_u32(&Bs[0][0][b_koff + lr][wn * 32 + nb * 16 + b_noff]);

    // cp.async load of one chunk into buffer bf
    auto load_chunk = [&](int chunk, int bf) {
        const int kk = chunk << 5;
        // A: 520 16B-units
        #pragma unroll
        for (int u = 0; u < 3; ++u) {
            int unit = tid + u * 256;
            if (unit < 520) {
                int row  = unit >> 2;
                int colu = (unit & 3) * 8;
                int t = t0 + row - 1;
                int tc = min(max(t, 0), TT - 1);
                uint32_t sz = (t >= 0 && t < TT) ? 16u : 0u;
                CP16Z(smem_u32(&As[bf][row][colu]),
                      Abase + (size_t)tc * CC + kk + colu, sz);
            }
        }
        // B: 768 16B-units (3 taps x 32 rows x 64 cols)
        #pragma unroll
        for (int u = 0; u < 3; ++u) {
            int unit = tid + u * 256;
            int tap = unit >> 8;
            int rem = unit & 255;
            int row  = rem >> 3;
            int colu = (rem & 7) * 8;
            CP16(smem_u32(&Bs[bf][tap][row][colu]),
                 Wbase + (size_t)tap * (CC * CC) + (size_t)(kk + row) * CC + colu);
        }
    };

    float acc[2][4][4];
    #pragma unroll
    for (int i = 0; i < 2; ++i)
        #pragma unroll
        for (int j = 0; j < 4; ++j)
            #pragma unroll
            for (int c = 0; c < 4; ++c) acc[i][j][c] = 0.f;

    load_chunk(0, 0);
    CP_COMMIT();

    for (int chunk = 0; chunk < 8; ++chunk) {
        const int buf = chunk & 1;
        if (chunk + 1 < 8) {
            load_chunk(chunk + 1, buf ^ 1);
            CP_COMMIT();
            CP_WAIT1();
        } else {
            CP_WAIT0();
        }
        __syncthreads();

        #pragma unroll
        for (int tap = 0; tap < 3; ++tap) {
            #pragma unroll
            for (int ks = 0; ks < 2; ++ks) {
                uint32_t a[2][4], b[2][4];
                #pragma unroll
                for (int mi = 0; mi < 2; ++mi)
                    ldm_x4(a[mi], a_base0[mi] + buf * AS_BUFB + tap * (AS_STRIDE * 2) + ks * 32);
                #pragma unroll
                for (int nb = 0; nb < 2; ++nb)
                    ldm_x4t(b[nb], b_base0[nb] + buf * BS_BUFB + tap * (32 * BS_STRIDE * 2) + ks * 16 * (BS_STRIDE * 2));
                #pragma unroll
                for (int mi = 0; mi < 2; ++mi)
                    #pragma unroll
                    for (int nj = 0; nj < 4; ++nj)
                        mma_f16(acc[mi][nj], a[mi],
                                b[nj >> 1][(nj & 1) * 2], b[nj >> 1][(nj & 1) * 2 + 1]);
            }
        }
        __syncthreads();
    }

    // Epilogue
    const float qscale = (!IS_OUT && mat == 0) ? 0.17677669529663687f : 1.0f;
    #pragma unroll
    for (int mi = 0; mi < 2; ++mi) {
        #pragma unroll
        for (int nj = 0; nj < 4; ++nj) {
            int row0 = m0 + wm * 32 + mi * 16 + g;
            int col  = wn * 32 + nj * 8 + 2 * tg;
            float b0 = bias[n0 + col];
            float b1 = bias[n0 + col + 1];
            if (IS_OUT) {
                size_t o0 = (size_t)row0 * CC + n0 + col;
                size_t o1 = (size_t)(row0 + 8) * CC + n0 + col;
                float2 r0 = *reinterpret_cast<const float2*>(Xres + o0);
                float2 r1 = *reinterpret_cast<const float2*>(Xres + o1);
                *reinterpret_cast<float2*>(Yout + o0) =
                    make_float2(acc[mi][nj][0] + b0 + r0.x, acc[mi][nj][1] + b1 + r0.y);
                *reinterpret_cast<float2*>(Yout + o1) =
                    make_float2(acc[mi][nj][2] + b0 + r1.x, acc[mi][nj][3] + b1 + r1.y);
            } else {
                size_t o0 = (size_t)row0 * 768 + mat * 256 + n0 + col;
                size_t o1 = (size_t)(row0 + 8) * 768 + mat * 256 + n0 + col;
                *reinterpret_cast<__half2*>(&g_qkv[o0]) =
                    __floats2half2_rn((acc[mi][nj][0] + b0) * qscale, (acc[mi][nj][1] + b1) * qscale);
                *reinterpret_cast<__half2*>(&g_qkv[o1]) =
                    __floats2half2_rn((acc[mi][nj][2] + b0) * qscale, (acc[mi][nj][3] + b1) * qscale);
            }
        }
    }
}

// ---------------------------------------------------------------------------
// Flash attention, fp16 mma, register P, cp.async double-buffered KV.
// grid (16 q-tiles, 64 b*h), block 128 (4 warps). Warp owns 32 q rows.
// ---------------------------------------------------------------------------
__global__ __launch_bounds__(128) void attn_mma_kernel()
{
    __shared__ __align__(16) __half Qs[128][40];
    __shared__ __align__(16) __half Ks[2][64][40];
    __shared__ __align__(16) __half Vs[2][64][40];

    const int tid = threadIdx.x;
    const int warp = tid >> 5;
    const int lane = tid & 31;
    const int g  = lane >> 2;
    const int tg = lane & 3;
    const int lr = lane & 7;

    const int qt = blockIdx.x;
    const int bh = blockIdx.y;
    const int bI = bh >> 3;
    const int h  = bh & 7;
    const int q0 = qt * 128;

    const __half* qp = g_qkv + (size_t)bI * TT * 768 + h * 32;
    const __half* kp = qp + 256;
    const __half* vp = qp + 512;

    const int a_roff = ((lane >> 3) & 1) * 8;
    const int a_coff = ((lane >> 4) & 1) * 8;
    const int kb_roff = ((lane >> 4) & 1) * 8;
    const int kb_coff = ((lane >> 3) & 1) * 8;
    const int vb_roff = ((lane >> 3) & 1) * 8;
    const int vb_coff = ((lane >> 4) & 1) * 8;

    uint32_t qa_base[2];
    #pragma unroll
    for (int mi = 0; mi < 2; ++mi)
        qa_base[mi] = smem_u32(&Qs[warp * 32 + mi * 16 + a_roff + lr][a_coff]);
    uint32_t kb_base[2][4], vb_base[2][2];
    #pragma unroll
    for (int bf = 0; bf < 2; ++bf) {
        #pragma unroll
        for (int n2 = 0; n2 < 4; ++n2)
            kb_base[bf][n2] = smem_u32(&Ks[bf][n2 * 16 + kb_roff + lr][kb_coff]);
        #pragma unroll
        for (int nb = 0; nb < 2; ++nb)
            vb_base[bf][nb] = smem_u32(&Vs[bf][vb_roff + lr][nb * 16 + vb_coff]);
    }

    // Q tile: 128 rows x 32 halves = 512 uint4, 4 per thread
    #pragma unroll
    for (int u = 0; u < 4; ++u) {
        int idx = tid + u * 128;
        int row = idx >> 2;
        int col = (idx & 3) * 8;
        *reinterpret_cast<uint4*>(&Qs[row][col]) =
            *reinterpret_cast<const uint4*>(qp + (size_t)(q0 + row) * 768 + col);
    }

    // KV tile: 256 uint4 each; 2 per thread per tile
    auto load_kv = [&](int jt, int bf) {
        #pragma unroll
        for (int u = 0; u < 2; ++u) {
            int idx = tid + u * 128;
            int row = idx >> 2;
            int col = (idx & 3) * 8;
            size_t roff = (size_t)(jt * 64 + row) * 768 + col;
            CP16(smem_u32(&Ks[bf][row][col]), kp + roff);
            CP16(smem_u32(&Vs[bf][row][col]), vp + roff);
        }
    };

    load_kv(0, 0);
    CP_COMMIT();
    __syncthreads();   // Qs visible

    uint32_t qa[2][2][4];
    #pragma unroll
    for (int mi = 0; mi < 2; ++mi) {
        ldm_x4(qa[mi][0], qa_base[mi]);
        ldm_x4(qa[mi][1], qa_base[mi] + 32);
    }

    float m_i[2][2], l_i[2][2], o[2][4][4];
    #pragma unroll
    for (int mi = 0; mi < 2; ++mi) {
        m_i[mi][0] = -1e30f; m_i[mi][1] = -1e30f;
        l_i[mi][0] = 0.f;    l_i[mi][1] = 0.f;
        #pragma unroll
        for (int nj = 0; nj < 4; ++nj)
            #pragma unroll
            for (int c = 0; c < 4; ++c) o[mi][nj][c] = 0.f;
    }

    for (int jt = 0; jt < 32; ++jt) {
        const int buf = jt & 1;
        if (jt + 1 < 32) {
            load_kv(jt + 1, buf ^ 1);
            CP_COMMIT();
            CP_WAIT1();
        } else {
            CP_WAIT0();
        }
        __syncthreads();

        // S = Q K^T : warp 32x64
        float s[2][8][4];
        #pragma unroll
        for (int mi = 0; mi < 2; ++mi)
            #pragma unroll
            for (int nj = 0; nj < 8; ++nj)
                #pragma unroll
                for (int c = 0; c < 4; ++c) s[mi][nj][c] = 0.f;
        #pragma unroll
        for (int ks = 0; ks < 2; ++ks) {
            #pragma unroll
            for (int n2 = 0; n2 < 4; ++n2) {
                uint32_t b[4];
                ldm_x4(b, kb_base[buf][n2] + ks * 32);
                #pragma unroll
                for (int mi = 0; mi < 2; ++mi) {
                    mma_f16(s[mi][n2 * 2],     qa[mi][ks], b[0], b[1]);
                    mma_f16(s[mi][n2 * 2 + 1], qa[mi][ks], b[2], b[3]);
                }
            }
        }

        // online softmax + pack P, per m-frag
        uint32_t pa[2][4][4];
        #pragma unroll
        for (int mi = 0; mi < 2; ++mi) {
            float mx0 = -1e30f, mx1 = -1e30f;
            #pragma unroll
            for (int nj = 0; nj < 8; ++nj) {
                mx0 = fmaxf(mx0, fmaxf(s[mi][nj][0], s[mi][nj][1]));
                mx1 = fmaxf(mx1, fmaxf(s[mi][nj][2], s[mi][nj][3]));
            }
            mx0 = fmaxf(mx0, __shfl_xor_sync(0xffffffffu, mx0, 1));
            mx0 = fmaxf(mx0, __shfl_xor_sync(0xffffffffu, mx0, 2));
            mx1 = fmaxf(mx1, __shfl_xor_sync(0xffffffffu, mx1, 1));
            mx1 = fmaxf(mx1, __shfl_xor_sync(0xffffffffu, mx1, 2));

            float mn0 = fmaxf(m_i[mi][0], mx0);
            float mn1 = fmaxf(m_i[mi][1], mx1);
            float corr0 = __expf(m_i[mi][0] - mn0);
            float corr1 = __expf(m_i[mi][1] - mn1);

            float sum0 = 0.f, sum1 = 0.f;
            #pragma unroll
            for (int nj = 0; nj < 8; ++nj) {
                s[mi][nj][0] = __expf(s[mi][nj][0] - mn0);
                s[mi][nj][1] = __expf(s[mi][nj][1] - mn0);
                s[mi][nj][2] = __expf(s[mi][nj][2] - mn1);
                s[mi][nj][3] = __expf(s[mi][nj][3] - mn1);
                sum0 += s[mi][nj][0] + s[mi][nj][1];
                sum1 += s[mi][nj][2] + s[mi][nj][3];
            }
            sum0 += __shfl_xor_sync(0xffffffffu, sum0, 1);
            sum0 += __shfl_xor_sync(0xffffffffu, sum0, 2);
            sum1 += __shfl_xor_sync(0xffffffffu, sum1, 1);
            sum1 += __shfl_xor_sync(0xffffffffu, sum1, 2);

            l_i[mi][0] = l_i[mi][0] * corr0 + sum0;
            l_i[mi][1] = l_i[mi][1] * corr1 + sum1;
            m_i[mi][0] = mn0; m_i[mi][1] = mn1;
            #pragma unroll
            for (int nj = 0; nj < 4; ++nj) {
                o[mi][nj][0] *= corr0; o[mi][nj][1] *= corr0;
                o[mi][nj][2] *= corr1; o[mi][nj][3] *= corr1;
            }
            #pragma unroll
            for (int kc = 0; kc < 4; ++kc) {
                pa[mi][kc][0] = h2pack(s[mi][2 * kc][0],     s[mi][2 * kc][1]);
                pa[mi][kc][1] = h2pack(s[mi][2 * kc][2],     s[mi][2 * kc][3]);
                pa[mi][kc][2] = h2pack(s[mi][2 * kc + 1][0], s[mi][2 * kc + 1][1]);
                pa[mi][kc][3] = h2pack(s[mi][2 * kc + 1][2], s[mi][2 * kc + 1][3]);
            }
        }

        // O += P V
        #pragma unroll
        for (int kc = 0; kc < 4; ++kc) {
            #pragma unroll
            for (int nb = 0; nb < 2; ++nb) {
                uint32_t b[4];
                ldm_x4t(b, vb_base[buf][nb] + kc * 16 * 80);
                #pragma unroll
                for (int mi = 0; mi < 2; ++mi) {
                    mma_f16(o[mi][nb * 2],     pa[mi][kc], b[0], b[1]);
                    mma_f16(o[mi][nb * 2 + 1], pa[mi][kc], b[2], b[3]);
                }
            }
        }
        __syncthreads();   // buf consumed before next prefetch overwrites
    }

    // normalize + write ctx (half)
    #pragma unroll
    for (int mi = 0; mi < 2; ++mi) {
        float inv0 = 1.0f / l_i[mi][0];
        float inv1 = 1.0f / l_i[mi][1];
        size_t row0 = (size_t)bI * TT + q0 + warp * 32 + mi * 16 + g;
        #pragma unroll
        for (int nj = 0; nj < 4; ++nj) {
            int col = h * 32 + nj * 8 + 2 * tg;
            *reinterpret_cast<__half2*>(&g_ctx[row0 * CC + col]) =
                __floats2half2_rn(o[mi][nj][0] * inv0, o[mi][nj][1] * inv0);
            *reinterpret_cast<__half2*>(&g_ctx[(row0 + 8) * CC + col]) =
                __floats2half2_rn(o[mi][nj][2] * inv1, o[mi][nj][3] * inv1);
        }
    }
}

// ---------------------------------------------------------------------------
extern "C" void kernel_launch(void* const* d_in, const int* in_sizes, int n_in,
                              void* d_out, int out_size)
{
    const float* x  = (const float*)d_in[0];
    const float* Wq = (const float*)d_in[1];
    const float* bq = (const float*)d_in[2];
    const float* Wk = (const float*)d_in[3];
    const float* bk = (const float*)d_in[4];
    const float* Wv = (const float*)d_in[5];
    const float* bv = (const float*)d_in[6];
    const float* Wo = (const float*)d_in[7];
    const float* bo = (const float*)d_in[8];
    float* out = (float*)d_out;

    cvt_kernel<<<2432, 256>>>(x, Wq, Wk, Wv, Wo);
    conv_mma_kernel<false><<<dim3(128, 12), 256>>>(nullptr, bq, bk, bv, nullptr);
    attn_mma_kernel<<<dim3(16, 64), 128>>>();
    conv_mma_kernel<true><<<dim3(128, 4), 256>>>(x, bo, nullptr, nullptr, out);
}

// round 8
// speedup vs baseline: 7.9327x; 1.1156x over previous
#include <cuda_runtime.h>
#include <cuda_fp16.h>
#include <cstdint>

#define TT 2048
#define CC 256
#define MTOT 16384   // 8 * 2048

// Scratch (allocation-free rule: device globals)
static __device__ __half g_qkv[MTOT * 768];        // q(pre-scaled, log2-domain)|k|v per row
static __device__ __half g_ctx[MTOT * CC];         // attention output
static __device__ __half g_xh[MTOT * CC];          // x converted to half
static __device__ __half g_wh[4 * 3 * CC * CC];    // Wq,Wk,Wv,Wo converted to half

// ---------------------------------------------------------------------------
__device__ __forceinline__ uint32_t smem_u32(const void* p) {
    return (uint32_t)__cvta_generic_to_shared(p);
}
__device__ __forceinline__ void ldm_x4(uint32_t* r, uint32_t addr) {
    asm volatile("ldmatrix.sync.aligned.m8n8.x4.shared.b16 {%0,%1,%2,%3}, [%4];"
                 : "=r"(r[0]), "=r"(r[1]), "=r"(r[2]), "=r"(r[3]) : "r"(addr));
}
__device__ __forceinline__ void ldm_x4t(uint32_t* r, uint32_t addr) {
    asm volatile("ldmatrix.sync.aligned.m8n8.x4.trans.shared.b16 {%0,%1,%2,%3}, [%4];"
                 : "=r"(r[0]), "=r"(r[1]), "=r"(r[2]), "=r"(r[3]) : "r"(addr));
}
__device__ __forceinline__ void mma_f16(float* d, const uint32_t* a, uint32_t b0, uint32_t b1) {
    asm volatile(
        "mma.sync.aligned.m16n8k16.row.col.f32.f16.f16.f32 "
        "{%0,%1,%2,%3}, {%4,%5,%6,%7}, {%8,%9}, {%0,%1,%2,%3};"
        : "+f"(d[0]), "+f"(d[1]), "+f"(d[2]), "+f"(d[3])
        : "r"(a[0]), "r"(a[1]), "r"(a[2]), "r"(a[3]), "r"(b0), "r"(b1));
}
__device__ __forceinline__ uint32_t h2pack(float a, float b) {
    __half2 h = __floats2half2_rn(a, b);
    return *reinterpret_cast<uint32_t*>(&h);
}
// 2^x for two packed values; input two f32, output packed fp16x2
__device__ __forceinline__ uint32_t ex2pack(float lo, float hi) {
    uint32_t h;
    asm("{.reg .b32 t;\n\t"
        "cvt.rn.f16x2.f32 t, %1, %2;\n\t"
        "ex2.approx.f16x2 %0, t;}\n\t"
        : "=r"(h) : "f"(hi), "f"(lo));
    return h;
}
__device__ __forceinline__ float ex2f(float x) {
    float r; asm("ex2.approx.f32 %0, %1;" : "=f"(r) : "f"(x)); return r;
}
#define CP16(dst, src) asm volatile("cp.async.cg.shared.global [%0], [%1], 16;" :: "r"(dst), "l"(src))
#define CP16Z(dst, src, sz) asm volatile("cp.async.cg.shared.global [%0], [%1], 16, %2;" :: "r"(dst), "l"(src), "r"(sz))
#define CP_COMMIT() asm volatile("cp.async.commit_group;")
#define CP_WAIT1() asm volatile("cp.async.wait_group 1;")
#define CP_WAIT0() asm volatile("cp.async.wait_group 0;")
#define ONES_H2 0x3C003C00u

// ---------------------------------------------------------------------------
// One-shot conversion: x -> g_xh, W{q,k,v,o} -> g_wh. Unit = 8 floats.
// ---------------------------------------------------------------------------
#define XUNITS 524288   // MTOT*CC/8
#define WUNITS_PER 24576
__global__ __launch_bounds__(256) void cvt_kernel(
    const float* __restrict__ x,
    const float* __restrict__ Wq, const float* __restrict__ Wk,
    const float* __restrict__ Wv, const float* __restrict__ Wo)
{
    int i = blockIdx.x * blockDim.x + threadIdx.x;
    const float* src;
    __half* dst;
    if (i < XUNITS) {
        src = x + (size_t)i * 8;
        dst = g_xh + (size_t)i * 8;
    } else {
        int w = i - XUNITS;
        if (w >= 4 * WUNITS_PER) return;
        int m = w / WUNITS_PER;
        int r = w - m * WUNITS_PER;
        const float* W = (m == 0) ? Wq : (m == 1) ? Wk : (m == 2) ? Wv : Wo;
        src = W + (size_t)r * 8;
        dst = g_wh + (size_t)m * (3 * CC * CC) + (size_t)r * 8;
    }
    float4 f0 = *reinterpret_cast<const float4*>(src);
    float4 f1 = *reinterpret_cast<const float4*>(src + 4);
    uint4 st;
    st.x = h2pack(f0.x, f0.y); st.y = h2pack(f0.z, f0.w);
    st.z = h2pack(f1.x, f1.y); st.w = h2pack(f1.z, f1.w);
    *reinterpret_cast<uint4*>(dst) = st;
}

// ---------------------------------------------------------------------------
// Conv-as-GEMM, fp16 mma, cp.async double-buffered.
// Block tile 128(M) x 64(N). A tile 130 rows reused by all 3 taps.
// 256 threads = 8 warps (4m x 2n), warp tile 32x32.
// ---------------------------------------------------------------------------
#define AS_STRIDE 40
#define BS_STRIDE 72
#define AS_BUFB (130 * AS_STRIDE * 2)
#define BS_BUFB (3 * 32 * BS_STRIDE * 2)

template <bool IS_OUT>
__global__ __launch_bounds__(256) void conv_mma_kernel(
    const float* __restrict__ Xres,
    const float* __restrict__ bq, const float* __restrict__ bk,
    const float* __restrict__ bv,
    float* __restrict__ Yout)
{
    __shared__ __align__(16) __half As[2][130][AS_STRIDE];
    __shared__ __align__(16) __half Bs[2][3][32][BS_STRIDE];

    const int tid = threadIdx.x;
    const int m0 = blockIdx.x * 128;
    const int bI = m0 >> 11;
    const int t0 = m0 & (TT - 1);

    int mat, n0;
    const float* bias;
    if (IS_OUT) {
        mat = 3; n0 = blockIdx.y * 64;
        bias = bq;                     // bo via bq slot
    } else {
        mat = blockIdx.y >> 2;
        n0 = (blockIdx.y & 3) * 64;
        bias = (mat == 0) ? bq : (mat == 1) ? bk : bv;
    }

    const __half* Abase = (IS_OUT ? g_ctx : g_xh) + (size_t)bI * TT * CC;
    const __half* Wbase = g_wh + (size_t)mat * (3 * CC * CC) + n0;

    const int warp = tid >> 5;
    const int lane = tid & 31;
    const int g  = lane >> 2;
    const int tg = lane & 3;
    const int wm = warp >> 1;
    const int wn = warp & 1;

    const int lr = lane & 7;
    const int a_roff = ((lane >> 3) & 1) * 8;
    const int a_coff = ((lane >> 4) & 1) * 8;
    const int b_koff = ((lane >> 3) & 1) * 8;
    const int b_noff = ((lane >> 4) & 1) * 8;

    uint32_t a_base0[2], b_base0[2];
    #pragma unroll
    for (int mi = 0; mi < 2; ++mi)
        a_base0[mi] = smem_u32(&As[0][wm * 32 + mi * 16 + a_roff + lr][a_coff]);
    #pragma unroll
    for (int nb = 0; nb < 2; ++nb)
        b_base0[nb] = smem_u32(&Bs[0][0][b_koff + lr][wn * 32 + nb * 16 + b_noff]);

    auto load_chunk = [&](int chunk, int bf) {
        const int kk = chunk << 5;
        #pragma unroll
        for (int u = 0; u < 3; ++u) {
            int unit = tid + u * 256;
            if (unit < 520) {
                int row  = unit >> 2;
                int colu = (unit & 3) * 8;
                int t = t0 + row - 1;
                int tc = min(max(t, 0), TT - 1);
                uint32_t sz = (t >= 0 && t < TT) ? 16u : 0u;
                CP16Z(smem_u32(&As[bf][row][colu]),
                      Abase + (size_t)tc * CC + kk + colu, sz);
            }
        }
        #pragma unroll
        for (int u = 0; u < 3; ++u) {
            int unit = tid + u * 256;
            int tap = unit >> 8;
            int rem = unit & 255;
            int row  = rem >> 3;
            int colu = (rem & 7) * 8;
            CP16(smem_u32(&Bs[bf][tap][row][colu]),
                 Wbase + (size_t)tap * (CC * CC) + (size_t)(kk + row) * CC + colu);
        }
    };

    float acc[2][4][4];
    #pragma unroll
    for (int i = 0; i < 2; ++i)
        #pragma unroll
        for (int j = 0; j < 4; ++j)
            #pragma unroll
            for (int c = 0; c < 4; ++c) acc[i][j][c] = 0.f;

    load_chunk(0, 0);
    CP_COMMIT();

    for (int chunk = 0; chunk < 8; ++chunk) {
        const int buf = chunk & 1;
        if (chunk + 1 < 8) {
            load_chunk(chunk + 1, buf ^ 1);
            CP_COMMIT();
            CP_WAIT1();
        } else {
            CP_WAIT0();
        }
        __syncthreads();

        #pragma unroll
        for (int tap = 0; tap < 3; ++tap) {
            #pragma unroll
            for (int ks = 0; ks < 2; ++ks) {
                uint32_t a[2][4], b[2][4];
                #pragma unroll
                for (int mi = 0; mi < 2; ++mi)
                    ldm_x4(a[mi], a_base0[mi] + buf * AS_BUFB + tap * (AS_STRIDE * 2) + ks * 32);
                #pragma unroll
                for (int nb = 0; nb < 2; ++nb)
                    ldm_x4t(b[nb], b_base0[nb] + buf * BS_BUFB + tap * (32 * BS_STRIDE * 2) + ks * 16 * (BS_STRIDE * 2));
                #pragma unroll
                for (int mi = 0; mi < 2; ++mi)
                    #pragma unroll
                    for (int nj = 0; nj < 4; ++nj)
                        mma_f16(acc[mi][nj], a[mi],
                                b[nj >> 1][(nj & 1) * 2], b[nj >> 1][(nj & 1) * 2 + 1]);
            }
        }
        __syncthreads();
    }

    // Epilogue. Q is pre-scaled by (1/sqrt(32))*log2(e) for log2-domain softmax.
    const float qscale = (!IS_OUT && mat == 0) ? 0.25503487f : 1.0f;
    #pragma unroll
    for (int mi = 0; mi < 2; ++mi) {
        #pragma unroll
        for (int nj = 0; nj < 4; ++nj) {
            int row0 = m0 + wm * 32 + mi * 16 + g;
            int col  = wn * 32 + nj * 8 + 2 * tg;
            float b0 = bias[n0 + col];
            float b1 = bias[n0 + col + 1];
            if (IS_OUT) {
                size_t o0 = (size_t)row0 * CC + n0 + col;
                size_t o1 = (size_t)(row0 + 8) * CC + n0 + col;
                float2 r0 = *reinterpret_cast<const float2*>(Xres + o0);
                float2 r1 = *reinterpret_cast<const float2*>(Xres + o1);
                *reinterpret_cast<float2*>(Yout + o0) =
                    make_float2(acc[mi][nj][0] + b0 + r0.x, acc[mi][nj][1] + b1 + r0.y);
                *reinterpret_cast<float2*>(Yout + o1) =
                    make_float2(acc[mi][nj][2] + b0 + r1.x, acc[mi][nj][3] + b1 + r1.y);
            } else {
                size_t o0 = (size_t)row0 * 768 + mat * 256 + n0 + col;
                size_t o1 = (size_t)(row0 + 8) * 768 + mat * 256 + n0 + col;
                *reinterpret_cast<__half2*>(&g_qkv[o0]) =
                    __floats2half2_rn((acc[mi][nj][0] + b0) * qscale, (acc[mi][nj][1] + b1) * qscale);
                *reinterpret_cast<__half2*>(&g_qkv[o1]) =
                    __floats2half2_rn((acc[mi][nj][2] + b0) * qscale, (acc[mi][nj][3] + b1) * qscale);
            }
        }
    }
}

// ---------------------------------------------------------------------------
// Flash attention, fp16 mma, register P, log2-domain softmax with f16x2 ex2,
// row sums via ones-mma. grid (16 q-tiles, 64 b*h), block 128 (4 warps).
// ---------------------------------------------------------------------------
__global__ __launch_bounds__(128) void attn_mma_kernel()
{
    __shared__ __align__(16) __half Qs[128][40];
    __shared__ __align__(16) __half Ks[2][64][40];
    __shared__ __align__(16) __half Vs[2][64][40];

    const int tid = threadIdx.x;
    const int warp = tid >> 5;
    const int lane = tid & 31;
    const int g  = lane >> 2;
    const int tg = lane & 3;
    const int lr = lane & 7;

    const int qt = blockIdx.x;
    const int bh = blockIdx.y;
    const int bI = bh >> 3;
    const int h  = bh & 7;
    const int q0 = qt * 128;

    const __half* qp = g_qkv + (size_t)bI * TT * 768 + h * 32;
    const __half* kp = qp + 256;
    const __half* vp = qp + 512;

    const int a_roff = ((lane >> 3) & 1) * 8;
    const int a_coff = ((lane >> 4) & 1) * 8;
    const int kb_roff = ((lane >> 4) & 1) * 8;
    const int kb_coff = ((lane >> 3) & 1) * 8;
    const int vb_roff = ((lane >> 3) & 1) * 8;
    const int vb_coff = ((lane >> 4) & 1) * 8;

    uint32_t qa_base[2];
    #pragma unroll
    for (int mi = 0; mi < 2; ++mi)
        qa_base[mi] = smem_u32(&Qs[warp * 32 + mi * 16 + a_roff + lr][a_coff]);
    uint32_t kb_base[2][4], vb_base[2][2];
    #pragma unroll
    for (int bf = 0; bf < 2; ++bf) {
        #pragma unroll
        for (int n2 = 0; n2 < 4; ++n2)
            kb_base[bf][n2] = smem_u32(&Ks[bf][n2 * 16 + kb_roff + lr][kb_coff]);
        #pragma unroll
        for (int nb = 0; nb < 2; ++nb)
            vb_base[bf][nb] = smem_u32(&Vs[bf][vb_roff + lr][nb * 16 + vb_coff]);
    }

    // Q tile: 128 rows x 32 halves = 512 uint4, 4 per thread
    #pragma unroll
    for (int u = 0; u < 4; ++u) {
        int idx = tid + u * 128;
        int row = idx >> 2;
        int col = (idx & 3) * 8;
        *reinterpret_cast<uint4*>(&Qs[row][col]) =
            *reinterpret_cast<const uint4*>(qp + (size_t)(q0 + row) * 768 + col);
    }

    auto load_kv = [&](int jt, int bf) {
        #pragma unroll
        for (int u = 0; u < 2; ++u) {
            int idx = tid + u * 128;
            int row = idx >> 2;
            int col = (idx & 3) * 8;
            size_t roff = (size_t)(jt * 64 + row) * 768 + col;
            CP16(smem_u32(&Ks[bf][row][col]), kp + roff);
            CP16(smem_u32(&Vs[bf][row][col]), vp + roff);
        }
    };

    load_kv(0, 0);
    CP_COMMIT();
    __syncthreads();   // Qs visible

    uint32_t qa[2][2][4];
    #pragma unroll
    for (int mi = 0; mi < 2; ++mi) {
        ldm_x4(qa[mi][0], qa_base[mi]);
        ldm_x4(qa[mi][1], qa_base[mi] + 32);
    }

    float m_i[2][2], l_i[2][2], o[2][4][4];
    #pragma unroll
    for (int mi = 0; mi < 2; ++mi) {
        m_i[mi][0] = -1e30f; m_i[mi][1] = -1e30f;
        l_i[mi][0] = 0.f;    l_i[mi][1] = 0.f;
        #pragma unroll
        for (int nj = 0; nj < 4; ++nj)
            #pragma unroll
            for (int c = 0; c < 4; ++c) o[mi][nj][c] = 0.f;
    }

    for (int jt = 0; jt < 32; ++jt) {
        const int buf = jt & 1;
        if (jt + 1 < 32) {
            load_kv(jt + 1, buf ^ 1);
            CP_COMMIT();
            CP_WAIT1();
        } else {
            CP_WAIT0();
        }
        __syncthreads();

        // S = Q K^T (log2 domain): warp 32x64
        float s[2][8][4];
        #pragma unroll
        for (int mi = 0; mi < 2; ++mi)
            #pragma unroll
            for (int nj = 0; nj < 8; ++nj)
                #pragma unroll
                for (int c = 0; c < 4; ++c) s[mi][nj][c] = 0.f;
        #pragma unroll
        for (int ks = 0; ks < 2; ++ks) {
            #pragma unroll
            for (int n2 = 0; n2 < 4; ++n2) {
                uint32_t b[4];
                ldm_x4(b, kb_base[buf][n2] + ks * 32);
                #pragma unroll
                for (int mi = 0; mi < 2; ++mi) {
                    mma_f16(s[mi][n2 * 2],     qa[mi][ks], b[0], b[1]);
                    mma_f16(s[mi][n2 * 2 + 1], qa[mi][ks], b[2], b[3]);
                }
            }
        }

        // online softmax in log2 domain; P packed directly via ex2.f16x2
        uint32_t pa[2][4][4];
        float ls[2][4];
        #pragma unroll
        for (int mi = 0; mi < 2; ++mi) {
            float mx0 = -1e30f, mx1 = -1e30f;
            #pragma unroll
            for (int nj = 0; nj < 8; ++nj) {
                mx0 = fmaxf(mx0, fmaxf(s[mi][nj][0], s[mi][nj][1]));
                mx1 = fmaxf(mx1, fmaxf(s[mi][nj][2], s[mi][nj][3]));
            }
            mx0 = fmaxf(mx0, __shfl_xor_sync(0xffffffffu, mx0, 1));
            mx0 = fmaxf(mx0, __shfl_xor_sync(0xffffffffu, mx0, 2));
            mx1 = fmaxf(mx1, __shfl_xor_sync(0xffffffffu, mx1, 1));
            mx1 = fmaxf(mx1, __shfl_xor_sync(0xffffffffu, mx1, 2));

            float mn0 = fmaxf(m_i[mi][0], mx0);
            float mn1 = fmaxf(m_i[mi][1], mx1);
            float corr0 = ex2f(m_i[mi][0] - mn0);
            float corr1 = ex2f(m_i[mi][1] - mn1);
            m_i[mi][0] = mn0; m_i[mi][1] = mn1;
            l_i[mi][0] *= corr0; l_i[mi][1] *= corr1;
            #pragma unroll
            for (int nj = 0; nj < 4; ++nj) {
                o[mi][nj][0] *= corr0; o[mi][nj][1] *= corr0;
                o[mi][nj][2] *= corr1; o[mi][nj][3] *= corr1;
            }
            // p = 2^(s - mn), two at a time, straight into PV A-fragments
            #pragma unroll
            for (int kc = 0; kc < 4; ++kc) {
                pa[mi][kc][0] = ex2pack(s[mi][2 * kc][0] - mn0,     s[mi][2 * kc][1] - mn0);
                pa[mi][kc][1] = ex2pack(s[mi][2 * kc][2] - mn1,     s[mi][2 * kc][3] - mn1);
                pa[mi][kc][2] = ex2pack(s[mi][2 * kc + 1][0] - mn0, s[mi][2 * kc + 1][1] - mn0);
                pa[mi][kc][3] = ex2pack(s[mi][2 * kc + 1][2] - mn1, s[mi][2 * kc + 1][3] - mn1);
            }
            ls[mi][0] = 0.f; ls[mi][1] = 0.f; ls[mi][2] = 0.f; ls[mi][3] = 0.f;
        }

        // O += P V, and row sums ls += P @ 1 (exact same fp16 P)
        #pragma unroll
        for (int kc = 0; kc < 4; ++kc) {
            #pragma unroll
            for (int mi = 0; mi < 2; ++mi)
                mma_f16(ls[mi], pa[mi][kc], ONES_H2, ONES_H2);
            #pragma unroll
            for (int nb = 0; nb < 2; ++nb) {
                uint32_t b[4];
                ldm_x4t(b, vb_base[buf][nb] + kc * 16 * 80);
                #pragma unroll
                for (int mi = 0; mi < 2; ++mi) {
                    mma_f16(o[mi][nb * 2],     pa[mi][kc], b[0], b[1]);
                    mma_f16(o[mi][nb * 2 + 1], pa[mi][kc], b[2], b[3]);
                }
            }
        }
        #pragma unroll
        for (int mi = 0; mi < 2; ++mi) {
            l_i[mi][0] += ls[mi][0];   // all c-cols of ones-mma equal the row sum
            l_i[mi][1] += ls[mi][2];
        }
        __syncthreads();   // buf consumed before next prefetch overwrites
    }

    // normalize + write ctx (half)
    #pragma unroll
    for (int mi = 0; mi < 2; ++mi) {
        float inv0 = 1.0f / l_i[mi][0];
        float inv1 = 1.0f / l_i[mi][1];
        size_t row0 = (size_t)bI * TT + q0 + warp * 32 + mi * 16 + g;
        #pragma unroll
        for (int nj = 0; nj < 4; ++nj) {
            int col = h * 32 + nj * 8 + 2 * tg;
            *reinterpret_cast<__half2*>(&g_ctx[row0 * CC + col]) =
                __floats2half2_rn(o[mi][nj][0] * inv0, o[mi][nj][1] * inv0);
            *reinterpret_cast<__half2*>(&g_ctx[(row0 + 8) * CC + col]) =
                __floats2half2_rn(o[mi][nj][2] * inv1, o[mi][nj][3] * inv1);
        }
    }
}

// ---------------------------------------------------------------------------
extern "C" void kernel_launch(void* const* d_in, const int* in_sizes, int n_in,
                              void* d_out, int out_size)
{
    const float* x  = (const float*)d_in[0];
    const float* Wq = (const float*)d_in[1];
    const float* bq = (const float*)d_in[2];
    const float* Wk = (const float*)d_in[3];
    const float* bk = (const float*)d_in[4];
    const float* Wv = (const float*)d_in[5];
    const float* bv = (const float*)d_in[6];
    const float* Wo = (const float*)d_in[7];
    const float* bo = (const float*)d_in[8];
    float* out = (float*)d_out;

    cvt_kernel<<<2432, 256>>>(x, Wq, Wk, Wv, Wo);
    conv_mma_kernel<false><<<dim3(128, 12), 256>>>(nullptr, bq, bk, bv, nullptr);
    attn_mma_kernel<<<dim3(16, 64), 128>>>();
    conv_mma_kernel<true><<<dim3(128, 4), 256>>>(x, bo, nullptr, nullptr, out);
}